// round 9
// baseline (speedup 1.0000x reference)
#include <cuda_runtime.h>
#include <mma.h>
using namespace nvcuda;

#define Bb   2
#define Tt   1024
#define Cc   1024
#define Hh   16
#define Dd   64
#define Pp   3
#define Ee   8
#define DFF  1024
#define NN   (Bb*Tt)          // 2048 tokens
#define C3   (3*Cc)           // 3072

// ---------------- scratch (static device allocations) ----------------
__device__ float g_qkv[NN*C3];
__device__ float g_cat[NN*C3];
__device__ float g_scores[Bb*Hh*Tt*Tt];
__device__ float g_attn[Bb*Hh*Tt*Tt];
__device__ float g_y[NN*Cc];
__device__ float g_xn[NN*Cc];
__device__ float g_mean[Bb*Cc];
__device__ float g_scale[Bb*Hh];
__device__ int   g_cursor[Ee];
__device__ int   g_tok[Ee*NN];
__device__ float g_wgt[Ee*NN];
__device__ float g_act[Ee*NN*DFF];
// RNA-rounded copies of harness inputs (rounded once per launch)
__device__ float r_x[NN*Cc];
__device__ float r_qkvw[Pp*C3*Cc];
__device__ float r_mw[Cc*C3];
__device__ float r_f1w[Ee*DFF*Cc];
__device__ float r_f2w[Ee*Cc*DFF];

typedef wmma::fragment<wmma::matrix_a, 16, 16, 8, wmma::precision::tf32, wmma::row_major> FragA;
typedef wmma::fragment<wmma::matrix_b, 16, 16, 8, wmma::precision::tf32, wmma::col_major> FragBc;
typedef wmma::fragment<wmma::matrix_b, 16, 16, 8, wmma::precision::tf32, wmma::row_major> FragBr;
typedef wmma::fragment<wmma::accumulator, 16, 16, 8, float> FragC;

__device__ __forceinline__ float f2tf32(float x) {
    float r; asm("cvt.rna.tf32.f32 %0, %1;" : "=f"(r) : "f"(x)); return r;
}

// ---------------- cp.async helpers ----------------
__device__ __forceinline__ void cp16(void* dst, const void* src) {
    unsigned ds = (unsigned)__cvta_generic_to_shared(dst);
    asm volatile("cp.async.cg.shared.global [%0], [%1], 16;" :: "r"(ds), "l"(src));
}
__device__ __forceinline__ void cp16p(void* dst, const void* src, bool pred) {
    unsigned ds = (unsigned)__cvta_generic_to_shared(dst);
    int sz = pred ? 16 : 0;
    asm volatile("cp.async.cg.shared.global [%0], [%1], 16, %2;" :: "r"(ds), "l"(src), "r"(sz));
}
#define CPCOMMIT asm volatile("cp.async.commit_group;")
#define CPWAIT0  asm volatile("cp.async.wait_group 0;")
#define CPWAIT1  asm volatile("cp.async.wait_group 1;")

#define SLOT 2560                 // 128*20 floats per tile slot
#define SMEM_ABT (6*SLOT*4)       // 61440 B: 3 A slots + 3 B slots
#define VSLOT 1088                // 16*68
#define SMEM_AV ((3*SLOT + 3*VSLOT)*4)   // 43776 B

// ---------------- block reductions ----------------
__device__ __forceinline__ float blockReduceSum(float v) {
    __shared__ float sh[8];
    int lane = threadIdx.x & 31, w = threadIdx.x >> 5;
    #pragma unroll
    for (int o = 16; o; o >>= 1) v += __shfl_xor_sync(0xffffffffu, v, o);
    if (lane == 0) sh[w] = v;
    __syncthreads();
    float r = 0.f;
    #pragma unroll
    for (int i = 0; i < 8; i++) r += sh[i];
    __syncthreads();
    return r;
}
__device__ __forceinline__ float blockReduceMax(float v) {
    __shared__ float sh[8];
    int lane = threadIdx.x & 31, w = threadIdx.x >> 5;
    #pragma unroll
    for (int o = 16; o; o >>= 1) v = fmaxf(v, __shfl_xor_sync(0xffffffffu, v, o));
    if (lane == 0) sh[w] = v;
    __syncthreads();
    float r = -1e30f;
    #pragma unroll
    for (int i = 0; i < 8; i++) r = fmaxf(r, sh[i]);
    __syncthreads();
    return r;
}

// ---------------- RNA pre-round (float4 grid-stride) ----------------
__global__ void k_round(const float4* __restrict__ src, float4* __restrict__ dst, int n4) {
    for (int i = blockIdx.x * blockDim.x + threadIdx.x; i < n4; i += gridDim.x * blockDim.x) {
        float4 t = src[i];
        t.x = f2tf32(t.x); t.y = f2tf32(t.y); t.z = f2tf32(t.z); t.w = f2tf32(t.w);
        dst[i] = t;
    }
}

// ========== generic C = A @ B^T, 128x128 tiles, wmma tf32, 3-stage cp.async ==========
__global__ __launch_bounds__(256) void k_gemm_abT(
    const float* __restrict__ A, int lda, long long sA1, long long sA2,
    const float* __restrict__ B, int ldb, long long sB1, long long sB2,
    const float* __restrict__ bias,
    float* __restrict__ C, int ldc, long long sC1, long long sC2,
    int K, int zdiv,
    const float* __restrict__ scale_z,
    const float* __restrict__ addsrc, int ldadd,
    int act, int rnd)
{
    extern __shared__ float dynsm[];
    int z = blockIdx.z, z1 = z / zdiv, z2 = z % zdiv;
    A += z1 * sA1 + z2 * sA2;
    B += z1 * sB1 + z2 * sB2;
    C += z1 * sC1 + z2 * sC2;
    const int m0 = blockIdx.x * 128, n0 = blockIdx.y * 128;
    const int tid = threadIdx.x, wid = tid >> 5, lane = tid & 31;
    const int mw = (wid >> 1) * 32, nw = (wid & 1) * 64;
    const int lr = tid >> 2, lc4 = (tid & 3) * 4;

    FragC acc[2][4];
    #pragma unroll
    for (int i = 0; i < 2; i++)
        #pragma unroll
        for (int j = 0; j < 4; j++) wmma::fill_fragment(acc[i][j], 0.f);

    const int nIter = K / 16;
    #pragma unroll
    for (int p = 0; p < 2; p++) {
        if (p < nIter) {
            int k0 = p * 16;
            float* As = dynsm + p * SLOT;
            float* Bs = dynsm + 3 * SLOT + p * SLOT;
            #pragma unroll
            for (int rep = 0; rep < 2; rep++) {
                int r = lr + rep * 64;
                cp16(&As[r * 20 + lc4], &A[(long long)(m0 + r) * lda + k0 + lc4]);
                cp16(&Bs[r * 20 + lc4], &B[(long long)(n0 + r) * ldb + k0 + lc4]);
            }
            CPCOMMIT;
        }
    }
    int sCur = 0;
    for (int i = 0; i < nIter; i++) {
        if (i + 1 < nIter) { CPWAIT1; } else { CPWAIT0; }
        __syncthreads();
        if (i + 2 < nIter) {
            int sPre = sCur + 2; if (sPre >= 3) sPre -= 3;
            int k0 = (i + 2) * 16;
            float* As = dynsm + sPre * SLOT;
            float* Bs = dynsm + 3 * SLOT + sPre * SLOT;
            #pragma unroll
            for (int rep = 0; rep < 2; rep++) {
                int r = lr + rep * 64;
                cp16(&As[r * 20 + lc4], &A[(long long)(m0 + r) * lda + k0 + lc4]);
                cp16(&Bs[r * 20 + lc4], &B[(long long)(n0 + r) * ldb + k0 + lc4]);
            }
            CPCOMMIT;
        }
        float* As = dynsm + sCur * SLOT;
        float* Bs = dynsm + 3 * SLOT + sCur * SLOT;
        #pragma unroll
        for (int s = 0; s < 2; s++) {
            FragA af[2];
            FragBc bf[4];
            #pragma unroll
            for (int ii = 0; ii < 2; ii++)
                wmma::load_matrix_sync(af[ii], &As[(mw + ii * 16) * 20 + s * 8], 20);
            #pragma unroll
            for (int j = 0; j < 4; j++)
                wmma::load_matrix_sync(bf[j], &Bs[(nw + j * 16) * 20 + s * 8], 20);
            #pragma unroll
            for (int ii = 0; ii < 2; ii++)
                #pragma unroll
                for (int j = 0; j < 4; j++)
                    wmma::mma_sync(acc[ii][j], af[ii], bf[j], acc[ii][j]);
        }
        sCur = (sCur == 2) ? 0 : sCur + 1;
    }
    __syncthreads();   // protect staging region (slot 0) from lagging warps
    float sc = scale_z ? scale_z[z] : 1.f;
    float* stage = dynsm + wid * 320;   // 16x20 per warp
    const int er = lane >> 1, ec0 = (lane & 1) * 8;
    #pragma unroll
    for (int i = 0; i < 2; i++) {
        #pragma unroll
        for (int j = 0; j < 4; j++) {
            wmma::store_matrix_sync(stage, acc[i][j], 20, wmma::mem_row_major);
            __syncwarp();
            int row = m0 + mw + i * 16 + er;
            int col = n0 + nw + j * 16 + ec0;
            float vals[8];
            #pragma unroll
            for (int q = 0; q < 8; q++) {
                float v = stage[er * 20 + ec0 + q] * sc;
                int nn = col + q;
                if (bias)   v += bias[nn];
                if (addsrc) v += addsrc[(long long)row * ldadd + nn];
                if (act)    v = v / (1.f + __expf(-v));
                if (rnd)    v = f2tf32(v);
                vals[q] = v;
            }
            *reinterpret_cast<float4*>(&C[(long long)row * ldc + col]) =
                make_float4(vals[0], vals[1], vals[2], vals[3]);
            *reinterpret_cast<float4*>(&C[(long long)row * ldc + col + 4]) =
                make_float4(vals[4], vals[5], vals[6], vals[7]);
            __syncwarp();
        }
    }
}

// ========== C = A @ B (row-major B, N=64), silu + RNA epilogue (AV) ==========
__global__ __launch_bounds__(256) void k_gemm_ab_silu(
    const float* __restrict__ A, int lda, long long sA1, long long sA2,
    const float* __restrict__ B, int ldb, long long sB1, long long sB2,
    float* __restrict__ C, int ldc, long long sC1, long long sC2,
    int K, int zdiv)
{
    extern __shared__ float dynsm[];
    int z = blockIdx.z, z1 = z / zdiv, z2 = z % zdiv;
    A += z1 * sA1 + z2 * sA2;
    B += z1 * sB1 + z2 * sB2;
    C += z1 * sC1 + z2 * sC2;
    const int m0 = blockIdx.x * 128;
    const int tid = threadIdx.x, wid = tid >> 5, lane = tid & 31;
    const int mw = (wid >> 1) * 32, nw = (wid & 1) * 32;
    const int lr = tid >> 2, lc4 = (tid & 3) * 4;
    const int vr = tid >> 4, vc4 = (tid & 15) * 4;
    float* Vbase = dynsm + 3 * SLOT;

    FragC acc[2][2];
    #pragma unroll
    for (int i = 0; i < 2; i++)
        #pragma unroll
        for (int j = 0; j < 2; j++) wmma::fill_fragment(acc[i][j], 0.f);

    const int nIter = K / 16;
    #pragma unroll
    for (int p = 0; p < 2; p++) {
        if (p < nIter) {
            int k0 = p * 16;
            float* As = dynsm + p * SLOT;
            float* Vs = Vbase + p * VSLOT;
            #pragma unroll
            for (int rep = 0; rep < 2; rep++) {
                int r = lr + rep * 64;
                cp16(&As[r * 20 + lc4], &A[(long long)(m0 + r) * lda + k0 + lc4]);
            }
            cp16(&Vs[vr * 68 + vc4], &B[(long long)(k0 + vr) * ldb + vc4]);
            CPCOMMIT;
        }
    }
    int sCur = 0;
    for (int i = 0; i < nIter; i++) {
        if (i + 1 < nIter) { CPWAIT1; } else { CPWAIT0; }
        __syncthreads();
        if (i + 2 < nIter) {
            int sPre = sCur + 2; if (sPre >= 3) sPre -= 3;
            int k0 = (i + 2) * 16;
            float* As = dynsm + sPre * SLOT;
            float* Vs = Vbase + sPre * VSLOT;
            #pragma unroll
            for (int rep = 0; rep < 2; rep++) {
                int r = lr + rep * 64;
                cp16(&As[r * 20 + lc4], &A[(long long)(m0 + r) * lda + k0 + lc4]);
            }
            cp16(&Vs[vr * 68 + vc4], &B[(long long)(k0 + vr) * ldb + vc4]);
            CPCOMMIT;
        }
        float* As = dynsm + sCur * SLOT;
        float* Vs = Vbase + sCur * VSLOT;
        #pragma unroll
        for (int s = 0; s < 2; s++) {
            FragA af[2];
            FragBr bf[2];
            #pragma unroll
            for (int ii = 0; ii < 2; ii++)
                wmma::load_matrix_sync(af[ii], &As[(mw + ii * 16) * 20 + s * 8], 20);
            #pragma unroll
            for (int j = 0; j < 2; j++)
                wmma::load_matrix_sync(bf[j], &Vs[(s * 8) * 68 + nw + j * 16], 68);
            #pragma unroll
            for (int ii = 0; ii < 2; ii++)
                #pragma unroll
                for (int j = 0; j < 2; j++)
                    wmma::mma_sync(acc[ii][j], af[ii], bf[j], acc[ii][j]);
        }
        sCur = (sCur == 2) ? 0 : sCur + 1;
    }
    __syncthreads();
    float* stage = dynsm + wid * 320;
    const int er = lane >> 1, ec0 = (lane & 1) * 8;
    #pragma unroll
    for (int i = 0; i < 2; i++) {
        #pragma unroll
        for (int j = 0; j < 2; j++) {
            wmma::store_matrix_sync(stage, acc[i][j], 20, wmma::mem_row_major);
            __syncwarp();
            int row = m0 + mw + i * 16 + er;
            int col = nw + j * 16 + ec0;
            float vals[8];
            #pragma unroll
            for (int q = 0; q < 8; q++) {
                float v = stage[er * 20 + ec0 + q];
                vals[q] = f2tf32(v / (1.f + __expf(-v)));
            }
            *reinterpret_cast<float4*>(&C[(long long)row * ldc + col]) =
                make_float4(vals[0], vals[1], vals[2], vals[3]);
            *reinterpret_cast<float4*>(&C[(long long)row * ldc + col + 4]) =
                make_float4(vals[4], vals[5], vals[6], vals[7]);
            __syncwarp();
        }
    }
}

// ---------------- small kernels ----------------
__global__ void k_colmean(const float* __restrict__ x, int lda) {
    int b = blockIdx.y;
    int c = blockIdx.x * 256 + threadIdx.x;
    const float* p = x + (long long)b * Tt * lda + c;
    float s = 0.f;
    for (int t = 0; t < Tt; t++) s += p[(long long)t * lda];
    g_mean[b * Cc + c] = s * (1.f / Tt);
}

__global__ void k_aware(const float* __restrict__ aw, const float* __restrict__ ab,
                        const float* __restrict__ ds) {
    int b = blockIdx.x >> 4, h = blockIdx.x & 15;
    const float* m = g_mean + b * Cc;
    const float* w = aw + h * Cc;
    float s = 0.f;
    for (int c = threadIdx.x; c < Cc; c += 256) s += m[c] * w[c];
    s = blockReduceSum(s);
    if (threadIdx.x == 0) g_scale[b * Hh + h] = ds[0] * (s + ab[h]);
}

__global__ void k_softmax_prior(int phase) {
    long long row = blockIdx.x;
    const float* s = g_scores + row * Tt;
    float* a = g_attn + row * Tt;
    int tid = threadIdx.x;
    float v[4];
    float mx = -1e30f;
    #pragma unroll
    for (int i = 0; i < 4; i++) { v[i] = s[tid + i * 256]; mx = fmaxf(mx, v[i]); }
    mx = blockReduceMax(mx);
    float sum = 0.f;
    #pragma unroll
    for (int i = 0; i < 4; i++) { v[i] = __expf(v[i] - mx); sum += v[i]; }
    sum = blockReduceSum(sum);
    float inv = 1.f / sum;
    #pragma unroll
    for (int i = 0; i < 4; i++) {
        float o = v[i] * inv;
        if (phase) o += 0.3f * a[tid + i * 256];
        a[tid + i * 256] = f2tf32(o);
    }
}

__global__ void k_layernorm(const float* __restrict__ gam, const float* __restrict__ bet,
                            float* __restrict__ out) {
    int row = blockIdx.x;
    const float* y = g_y + (long long)row * Cc;
    float s = 0.f, q = 0.f;
    for (int c = threadIdx.x; c < Cc; c += 256) { float v = y[c]; s += v; q += v * v; }
    s = blockReduceSum(s);
    q = blockReduceSum(q);
    float mu = s * (1.f / Cc);
    float var = q * (1.f / Cc) - mu * mu;
    float inv = rsqrtf(var + 1e-5f);
    for (int c = threadIdx.x; c < Cc; c += 256) {
        float xn = (y[c] - mu) * inv * gam[c] + bet[c];
        g_xn[(long long)row * Cc + c] = f2tf32(xn);   // rounded copy for GEMM input
        out[(long long)row * Cc + c] = xn;            // exact for output
    }
}

__global__ void k_zero() { if (threadIdx.x < Ee) g_cursor[threadIdx.x] = 0; }

__global__ void k_gate(const float* __restrict__ gw) {
    int n = blockIdx.x;
    int wid = threadIdx.x >> 5, lane = threadIdx.x & 31;
    __shared__ float lg[Ee];
    const float* t = g_xn + (long long)n * Cc;
    const float* w = gw + wid * Cc;
    float s = 0.f;
    for (int c = lane; c < Cc; c += 32) s += t[c] * w[c];
    #pragma unroll
    for (int o = 16; o; o >>= 1) s += __shfl_xor_sync(0xffffffffu, s, o);
    if (lane == 0) lg[wid] = s;
    __syncthreads();
    if (threadIdx.x == 0) {
        float mx = lg[0];
        #pragma unroll
        for (int e = 1; e < Ee; e++) mx = fmaxf(mx, lg[e]);
        float p[Ee];
        #pragma unroll
        for (int e = 0; e < Ee; e++) p[e] = __expf(lg[e] - mx);
        int i1 = 0;
        #pragma unroll
        for (int e = 1; e < Ee; e++) if (p[e] > p[i1]) i1 = e;
        int i2 = (i1 == 0) ? 1 : 0;
        #pragma unroll
        for (int e = 0; e < Ee; e++) if (e != i1 && p[e] > p[i2]) i2 = e;
        float tot = p[i1] + p[i2];
        float w1 = p[i1] / tot, w2 = p[i2] / tot;
        int p1 = atomicAdd(&g_cursor[i1], 1);
        g_tok[i1 * NN + p1] = n; g_wgt[i1 * NN + p1] = w1;
        int p2 = atomicAdd(&g_cursor[i2], 1);
        g_tok[i2 * NN + p2] = n; g_wgt[i2 * NN + p2] = w2;
    }
}

// ========== gathered expert FC1, wmma tf32, 3-stage, a = h^2*sigmoid(h), RNA out ==========
__global__ __launch_bounds__(256) void k_fc1(const float* __restrict__ fc1w,
                                             const float* __restrict__ fc1b) {
    extern __shared__ float dynsm[];
    int e = blockIdx.z;
    int cnt = g_cursor[e];
    int m0 = blockIdx.x * 128;
    if (m0 >= cnt) return;
    int n0 = blockIdx.y * 128;
    const float* Bw = fc1w + (long long)e * DFF * Cc;
    __shared__ int toks[128];
    const int tid = threadIdx.x, wid = tid >> 5, lane = tid & 31;
    const int mw = (wid >> 1) * 32, nw = (wid & 1) * 64;
    const int lr = tid >> 2, lc4 = (tid & 3) * 4;
    if (tid < 128) {
        int m = m0 + tid;
        toks[tid] = (m < cnt) ? g_tok[e * NN + m] : -1;
    }
    __syncthreads();
    FragC acc[2][4];
    #pragma unroll
    for (int i = 0; i < 2; i++)
        #pragma unroll
        for (int j = 0; j < 4; j++) wmma::fill_fragment(acc[i][j], 0.f);

    const int nIter = Cc / 16;
    #pragma unroll
    for (int p = 0; p < 2; p++) {
        int k0 = p * 16;
        float* As = dynsm + p * SLOT;
        float* Bs = dynsm + 3 * SLOT + p * SLOT;
        #pragma unroll
        for (int rep = 0; rep < 2; rep++) {
            int r = lr + rep * 64;
            int tk = toks[r];
            cp16p(&As[r * 20 + lc4], &g_xn[(long long)(tk < 0 ? 0 : tk) * Cc + k0 + lc4], tk >= 0);
            cp16(&Bs[r * 20 + lc4], &Bw[(long long)(n0 + r) * Cc + k0 + lc4]);
        }
        CPCOMMIT;
    }
    int sCur = 0;
    for (int i = 0; i < nIter; i++) {
        if (i + 1 < nIter) { CPWAIT1; } else { CPWAIT0; }
        __syncthreads();
        if (i + 2 < nIter) {
            int sPre = sCur + 2; if (sPre >= 3) sPre -= 3;
            int k0 = (i + 2) * 16;
            float* As = dynsm + sPre * SLOT;
            float* Bs = dynsm + 3 * SLOT + sPre * SLOT;
            #pragma unroll
            for (int rep = 0; rep < 2; rep++) {
                int r = lr + rep * 64;
                int tk = toks[r];
                cp16p(&As[r * 20 + lc4], &g_xn[(long long)(tk < 0 ? 0 : tk) * Cc + k0 + lc4], tk >= 0);
                cp16(&Bs[r * 20 + lc4], &Bw[(long long)(n0 + r) * Cc + k0 + lc4]);
            }
            CPCOMMIT;
        }
        float* As = dynsm + sCur * SLOT;
        float* Bs = dynsm + 3 * SLOT + sCur * SLOT;
        #pragma unroll
        for (int s = 0; s < 2; s++) {
            FragA af[2];
            FragBc bf[4];
            #pragma unroll
            for (int ii = 0; ii < 2; ii++)
                wmma::load_matrix_sync(af[ii], &As[(mw + ii * 16) * 20 + s * 8], 20);
            #pragma unroll
            for (int j = 0; j < 4; j++)
                wmma::load_matrix_sync(bf[j], &Bs[(nw + j * 16) * 20 + s * 8], 20);
            #pragma unroll
            for (int ii = 0; ii < 2; ii++)
                #pragma unroll
                for (int j = 0; j < 4; j++)
                    wmma::mma_sync(acc[ii][j], af[ii], bf[j], acc[ii][j]);
        }
        sCur = (sCur == 2) ? 0 : sCur + 1;
    }
    __syncthreads();
    const float* bp = fc1b + e * DFF;
    float* stage = dynsm + wid * 320;
    const int er = lane >> 1, ec0 = (lane & 1) * 8;
    #pragma unroll
    for (int i = 0; i < 2; i++) {
        #pragma unroll
        for (int j = 0; j < 4; j++) {
            wmma::store_matrix_sync(stage, acc[i][j], 20, wmma::mem_row_major);
            __syncwarp();
            int m = m0 + mw + i * 16 + er;
            if (m < cnt) {
                int n = n0 + nw + j * 16 + ec0;
                float vals[8];
                #pragma unroll
                for (int q = 0; q < 8; q++) {
                    float h = stage[er * 20 + ec0 + q] + bp[n + q];
                    vals[q] = f2tf32(h * h / (1.f + __expf(-h)));   // h * silu(h)
                }
                float* op = &g_act[((long long)e * NN + m) * DFF + n];
                *reinterpret_cast<float4*>(op) = make_float4(vals[0], vals[1], vals[2], vals[3]);
                *reinterpret_cast<float4*>(op + 4) = make_float4(vals[4], vals[5], vals[6], vals[7]);
            }
            __syncwarp();
        }
    }
}

// ========== gathered expert FC2 + weighted scatter-add, wmma tf32, 3-stage ==========
__global__ __launch_bounds__(256) void k_fc2(const float* __restrict__ fc2w,
                                             const float* __restrict__ fc2b,
                                             float* __restrict__ out) {
    extern __shared__ float dynsm[];
    int e = blockIdx.z;
    int cnt = g_cursor[e];
    int m0 = blockIdx.x * 128;
    if (m0 >= cnt) return;
    int n0 = blockIdx.y * 128;
    const float* Aa = g_act + (long long)e * NN * DFF;
    const float* Bw = fc2w + (long long)e * Cc * DFF;
    const int tid = threadIdx.x, wid = tid >> 5, lane = tid & 31;
    const int mw = (wid >> 1) * 32, nw = (wid & 1) * 64;
    const int lr = tid >> 2, lc4 = (tid & 3) * 4;
    FragC acc[2][4];
    #pragma unroll
    for (int i = 0; i < 2; i++)
        #pragma unroll
        for (int j = 0; j < 4; j++) wmma::fill_fragment(acc[i][j], 0.f);

    const int nIter = DFF / 16;
    #pragma unroll
    for (int p = 0; p < 2; p++) {
        int k0 = p * 16;
        float* As = dynsm + p * SLOT;
        float* Bs = dynsm + 3 * SLOT + p * SLOT;
        #pragma unroll
        for (int rep = 0; rep < 2; rep++) {
            int r = lr + rep * 64;
            cp16p(&As[r * 20 + lc4], &Aa[(long long)(m0 + r) * DFF + k0 + lc4], m0 + r < cnt);
            cp16(&Bs[r * 20 + lc4], &Bw[(long long)(n0 + r) * DFF + k0 + lc4]);
        }
        CPCOMMIT;
    }
    int sCur = 0;
    for (int i = 0; i < nIter; i++) {
        if (i + 1 < nIter) { CPWAIT1; } else { CPWAIT0; }
        __syncthreads();
        if (i + 2 < nIter) {
            int sPre = sCur + 2; if (sPre >= 3) sPre -= 3;
            int k0 = (i + 2) * 16;
            float* As = dynsm + sPre * SLOT;
            float* Bs = dynsm + 3 * SLOT + sPre * SLOT;
            #pragma unroll
            for (int rep = 0; rep < 2; rep++) {
                int r = lr + rep * 64;
                cp16p(&As[r * 20 + lc4], &Aa[(long long)(m0 + r) * DFF + k0 + lc4], m0 + r < cnt);
                cp16(&Bs[r * 20 + lc4], &Bw[(long long)(n0 + r) * DFF + k0 + lc4]);
            }
            CPCOMMIT;
        }
        float* As = dynsm + sCur * SLOT;
        float* Bs = dynsm + 3 * SLOT + sCur * SLOT;
        #pragma unroll
        for (int s = 0; s < 2; s++) {
            FragA af[2];
            FragBc bf[4];
            #pragma unroll
            for (int ii = 0; ii < 2; ii++)
                wmma::load_matrix_sync(af[ii], &As[(mw + ii * 16) * 20 + s * 8], 20);
            #pragma unroll
            for (int j = 0; j < 4; j++)
                wmma::load_matrix_sync(bf[j], &Bs[(nw + j * 16) * 20 + s * 8], 20);
            #pragma unroll
            for (int ii = 0; ii < 2; ii++)
                #pragma unroll
                for (int j = 0; j < 4; j++)
                    wmma::mma_sync(acc[ii][j], af[ii], bf[j], acc[ii][j]);
        }
        sCur = (sCur == 2) ? 0 : sCur + 1;
    }
    __syncthreads();
    const float* bp = fc2b + e * Cc;
    float* stage = dynsm + wid * 320;
    const int er = lane >> 1, ec0 = (lane & 1) * 8;
    #pragma unroll
    for (int i = 0; i < 2; i++) {
        #pragma unroll
        for (int j = 0; j < 4; j++) {
            wmma::store_matrix_sync(stage, acc[i][j], 20, wmma::mem_row_major);
            __syncwarp();
            int m = m0 + mw + i * 16 + er;
            if (m < cnt) {
                int tk = g_tok[e * NN + m];
                float w = g_wgt[e * NN + m] * 0.5f;   // * RATIO
                int n = n0 + nw + j * 16 + ec0;
                #pragma unroll
                for (int q = 0; q < 8; q++) {
                    atomicAdd(&out[(long long)tk * Cc + n + q],
                              (stage[er * 20 + ec0 + q] + bp[n + q]) * w);
                }
            }
            __syncwarp();
        }
    }
}

// ---------------- launch ----------------
extern "C" void kernel_launch(void* const* d_in, const int* in_sizes, int n_in,
                              void* d_out, int out_size) {
    (void)in_sizes; (void)n_in; (void)out_size;
    const float* x       = (const float*)d_in[0];
    const float* qkv_w   = (const float*)d_in[1];
    const float* qkv_b   = (const float*)d_in[2];
    const float* aware_w = (const float*)d_in[3];
    const float* aware_b = (const float*)d_in[4];
    const float* dyn     = (const float*)d_in[5];
    const float* mw      = (const float*)d_in[6];
    const float* mb      = (const float*)d_in[7];
    const float* lng     = (const float*)d_in[8];
    const float* lnb     = (const float*)d_in[9];
    const float* gw      = (const float*)d_in[10];
    const float* f1w     = (const float*)d_in[11];
    const float* f1b     = (const float*)d_in[12];
    const float* f2w     = (const float*)d_in[13];
    const float* f2b     = (const float*)d_in[14];
    float* out = (float*)d_out;

    cudaFuncSetAttribute(k_gemm_abT,    cudaFuncAttributeMaxDynamicSharedMemorySize, SMEM_ABT);
    cudaFuncSetAttribute(k_gemm_ab_silu,cudaFuncAttributeMaxDynamicSharedMemorySize, SMEM_AV);
    cudaFuncSetAttribute(k_fc1,         cudaFuncAttributeMaxDynamicSharedMemorySize, SMEM_ABT);
    cudaFuncSetAttribute(k_fc2,         cudaFuncAttributeMaxDynamicSharedMemorySize, SMEM_ABT);

    float *catp, *qkvp, *scoresp, *attnp, *yp, *scalep;
    float *rxp, *rqwp, *rmwp, *rf1p, *rf2p;
    cudaGetSymbolAddress((void**)&catp,    g_cat);
    cudaGetSymbolAddress((void**)&qkvp,    g_qkv);
    cudaGetSymbolAddress((void**)&scoresp, g_scores);
    cudaGetSymbolAddress((void**)&attnp,   g_attn);
    cudaGetSymbolAddress((void**)&yp,      g_y);
    cudaGetSymbolAddress((void**)&scalep,  g_scale);
    cudaGetSymbolAddress((void**)&rxp,     r_x);
    cudaGetSymbolAddress((void**)&rqwp,    r_qkvw);
    cudaGetSymbolAddress((void**)&rmwp,    r_mw);
    cudaGetSymbolAddress((void**)&rf1p,    r_f1w);
    cudaGetSymbolAddress((void**)&rf2p,    r_f2w);

    // RNA pre-round of all harness-provided GEMM operands
    k_round<<<2048, 256>>>((const float4*)x,     (float4*)rxp,  NN*Cc/4);
    k_round<<<2048, 256>>>((const float4*)qkv_w, (float4*)rqwp, Pp*C3*Cc/4);
    k_round<<<2048, 256>>>((const float4*)mw,    (float4*)rmwp, Cc*C3/4);
    k_round<<<2048, 256>>>((const float4*)f1w,   (float4*)rf1p, Ee*DFF*Cc/4);
    k_round<<<2048, 256>>>((const float4*)f2w,   (float4*)rf2p, Ee*Cc*DFF/4);

    for (int i = 0; i < Pp; i++) {
        const float* xin = (i == 0) ? rxp : (catp + (i - 1) * Cc);
        int ldx = (i == 0) ? Cc : C3;

        k_colmean<<<dim3(Cc / 256, Bb), 256>>>(xin, ldx);
        k_aware<<<Bb * Hh, 256>>>(aware_w + (long long)i * Hh * Cc,
                                  aware_b + i * Hh, dyn + i);
        // qkv: (2048 x 1024) @ (3072 x 1024)^T + b -> g_qkv (RNA-rounded out)
        k_gemm_abT<<<dim3(NN / 128, C3 / 128, 1), 256, SMEM_ABT>>>(
            xin, ldx, 0, 0,
            rqwp + (long long)i * C3 * Cc, Cc, 0, 0,
            qkv_b + (long long)i * C3,
            qkvp, C3, 0, 0,
            Cc, 1, nullptr, nullptr, 0, 0, 1);
        // scores: per (b,h): Q(1024x64) @ K^T, scaled by g_scale[z] (exact out)
        k_gemm_abT<<<dim3(Tt / 128, Tt / 128, Bb * Hh), 256, SMEM_ABT>>>(
            qkvp,       C3, (long long)Tt * C3, Dd,
            qkvp + Cc,  C3, (long long)Tt * C3, Dd,
            nullptr,
            scoresp, Tt, (long long)Hh * Tt * Tt, (long long)Tt * Tt,
            Dd, Hh, scalep, nullptr, 0, 0, 0);
        // softmax + prior recurrence (writes g_attn, RNA-rounded)
        k_softmax_prior<<<Bb * Hh * Tt, 256>>>(i);
        // AV: attn(1024x1024) @ V(1024x64), silu+RNA, -> g_cat[:, i*C ...]
        k_gemm_ab_silu<<<dim3(Tt / 128, 1, Bb * Hh), 256, SMEM_AV>>>(
            attnp,          Tt, (long long)Hh * Tt * Tt, (long long)Tt * Tt,
            qkvp + 2 * Cc,  C3, (long long)Tt * C3, Dd,
            catp + i * Cc,  C3, (long long)Tt * C3, Dd,
            Tt, Hh);
    }

    // merger: (2048 x 3072) @ (1024 x 3072)^T + b + residual(exact x) -> g_y (exact)
    k_gemm_abT<<<dim3(NN / 128, Cc / 128, 1), 256, SMEM_ABT>>>(
        catp, C3, 0, 0,
        rmwp, C3, 0, 0,
        mb,
        yp, Cc, 0, 0,
        C3, 1, nullptr, x, Cc, 0, 0);

    k_layernorm<<<NN, 256>>>(lng, lnb, out);   // g_xn rounded, d_out exact
    k_zero<<<1, 32>>>();
    k_gate<<<NN, 256>>>(gw);
    k_fc1<<<dim3(NN / 128, DFF / 128, Ee), 256, SMEM_ABT>>>(rf1p, f1b);
    k_fc2<<<dim3(NN / 128, Cc / 128, Ee), 256, SMEM_ABT>>>(rf2p, f2b, out);
}

// round 11
// speedup vs baseline: 1.9633x; 1.9633x over previous
#include <cuda_runtime.h>
#include <cuda_fp16.h>
#include <mma.h>
using namespace nvcuda;

#define Bb   2
#define Tt   1024
#define Cc   1024
#define Hh   16
#define Dd   64
#define Pp   3
#define Ee   8
#define DFF  1024
#define NN   (Bb*Tt)          // 2048 tokens
#define C3   (3*Cc)           // 3072

// ---------------- scratch (static device allocations) ----------------
__device__ __half g_qkv[NN*C3];
__device__ __half g_cat[NN*C3];
__device__ __half g_scores[Bb*Hh*Tt*Tt];
__device__ __half g_attn[Bb*Hh*Tt*Tt];
__device__ float  g_y[NN*Cc];
__device__ __half g_xn[NN*Cc];          // half copy for GEMM/gate inputs
__device__ float  g_mean[Bb*Cc];
__device__ float  g_scale[Bb*Hh];
__device__ int    g_cursor[Ee];
__device__ int    g_tok[Ee*NN];
__device__ float  g_wgt[Ee*NN];
__device__ __half g_act[Ee*NN*DFF];
// half copies of harness inputs (converted once per launch)
__device__ __half r_x[NN*Cc];
__device__ __half r_qkvw[Pp*C3*Cc];
__device__ __half r_mw[Cc*C3];
__device__ __half r_f1w[Ee*DFF*Cc];
__device__ __half r_f2w[Ee*Cc*DFF];

typedef wmma::fragment<wmma::matrix_a, 16, 16, 16, __half, wmma::row_major> FragA;
typedef wmma::fragment<wmma::matrix_b, 16, 16, 16, __half, wmma::col_major> FragBc;
typedef wmma::fragment<wmma::matrix_b, 16, 16, 16, __half, wmma::row_major> FragBr;
typedef wmma::fragment<wmma::accumulator, 16, 16, 16, float> FragC;

// ---------------- cp.async helpers ----------------
__device__ __forceinline__ void cp16(void* dst, const void* src) {
    unsigned ds = (unsigned)__cvta_generic_to_shared(dst);
    asm volatile("cp.async.cg.shared.global [%0], [%1], 16;" :: "r"(ds), "l"(src));
}
__device__ __forceinline__ void cp16p(void* dst, const void* src, bool pred) {
    unsigned ds = (unsigned)__cvta_generic_to_shared(dst);
    int sz = pred ? 16 : 0;
    asm volatile("cp.async.cg.shared.global [%0], [%1], 16, %2;" :: "r"(ds), "l"(src), "r"(sz));
}
#define CPCOMMIT asm volatile("cp.async.commit_group;")
#define CPWAIT0  asm volatile("cp.async.wait_group 0;")
#define CPWAIT1  asm volatile("cp.async.wait_group 1;")

#define KT   32                   // k-tile depth (halves)
#define LDH  40                   // row stride in halves (32 + 8 pad, mult of 8)
#define SLOT (128*LDH)            // 5120 halves per tile slot
#define SMEM_ABT (6*SLOT*2)       // 61440 B
#define VLD  72
#define VSLOT (32*VLD)            // 2304 halves
#define SMEM_AV ((3*SLOT + 3*VSLOT)*2)   // 44544 B

// ---------------- block reductions ----------------
__device__ __forceinline__ float blockReduceSum(float v) {
    __shared__ float sh[8];
    int lane = threadIdx.x & 31, w = threadIdx.x >> 5;
    #pragma unroll
    for (int o = 16; o; o >>= 1) v += __shfl_xor_sync(0xffffffffu, v, o);
    if (lane == 0) sh[w] = v;
    __syncthreads();
    float r = 0.f;
    #pragma unroll
    for (int i = 0; i < 8; i++) r += sh[i];
    __syncthreads();
    return r;
}
__device__ __forceinline__ float blockReduceMax(float v) {
    __shared__ float sh[8];
    int lane = threadIdx.x & 31, w = threadIdx.x >> 5;
    #pragma unroll
    for (int o = 16; o; o >>= 1) v = fmaxf(v, __shfl_xor_sync(0xffffffffu, v, o));
    if (lane == 0) sh[w] = v;
    __syncthreads();
    float r = -1e30f;
    #pragma unroll
    for (int i = 0; i < 8; i++) r = fmaxf(r, sh[i]);
    __syncthreads();
    return r;
}

// ---------------- float -> half convert (float4 -> 4 halves) ----------------
__global__ void k_cvt(const float4* __restrict__ src, uint2* __restrict__ dst, int n4) {
    for (int i = blockIdx.x * blockDim.x + threadIdx.x; i < n4; i += gridDim.x * blockDim.x) {
        float4 t = src[i];
        __half2 h0 = __floats2half2_rn(t.x, t.y);
        __half2 h1 = __floats2half2_rn(t.z, t.w);
        uint2 o;
        o.x = *reinterpret_cast<unsigned*>(&h0);
        o.y = *reinterpret_cast<unsigned*>(&h1);
        dst[i] = o;
    }
}

// ========== generic C = A @ B^T, 128x128 tiles, fp16 wmma, 3-stage cp.async ==========
__global__ __launch_bounds__(256) void k_gemm_abT(
    const __half* __restrict__ A, int lda, long long sA1, long long sA2,
    const __half* __restrict__ B, int ldb, long long sB1, long long sB2,
    const float* __restrict__ bias,
    void* __restrict__ Cv, int ldc, long long sC1, long long sC2,
    int K, int zdiv,
    const float* __restrict__ scale_z,
    const float* __restrict__ addsrc, int ldadd,
    int act, int out_half)
{
    extern __shared__ __half dynsm[];
    int z = blockIdx.z, z1 = z / zdiv, z2 = z % zdiv;
    A += z1 * sA1 + z2 * sA2;
    B += z1 * sB1 + z2 * sB2;
    const int m0 = blockIdx.x * 128, n0 = blockIdx.y * 128;
    const int tid = threadIdx.x, wid = tid >> 5, lane = tid & 31;
    const int mw = (wid >> 1) * 32, nw = (wid & 1) * 64;
    const int lr = tid >> 1, ls = tid & 1;   // row 0..127, base seg 0/1

    FragC acc[2][4];
    #pragma unroll
    for (int i = 0; i < 2; i++)
        #pragma unroll
        for (int j = 0; j < 4; j++) wmma::fill_fragment(acc[i][j], 0.f);

    const int nIter = K / KT;
    #pragma unroll
    for (int p = 0; p < 2; p++) {
        if (p < nIter) {
            int k0 = p * KT;
            __half* As = dynsm + p * SLOT;
            __half* Bs = dynsm + 3 * SLOT + p * SLOT;
            #pragma unroll
            for (int rep = 0; rep < 2; rep++) {
                int seg = ls + rep * 2;
                cp16(&As[lr * LDH + seg * 8], &A[(long long)(m0 + lr) * lda + k0 + seg * 8]);
                cp16(&Bs[lr * LDH + seg * 8], &B[(long long)(n0 + lr) * ldb + k0 + seg * 8]);
            }
            CPCOMMIT;
        }
    }
    int sCur = 0;
    for (int i = 0; i < nIter; i++) {
        if (i + 1 < nIter) { CPWAIT1; } else { CPWAIT0; }
        __syncthreads();
        if (i + 2 < nIter) {
            int sPre = sCur + 2; if (sPre >= 3) sPre -= 3;
            int k0 = (i + 2) * KT;
            __half* As = dynsm + sPre * SLOT;
            __half* Bs = dynsm + 3 * SLOT + sPre * SLOT;
            #pragma unroll
            for (int rep = 0; rep < 2; rep++) {
                int seg = ls + rep * 2;
                cp16(&As[lr * LDH + seg * 8], &A[(long long)(m0 + lr) * lda + k0 + seg * 8]);
                cp16(&Bs[lr * LDH + seg * 8], &B[(long long)(n0 + lr) * ldb + k0 + seg * 8]);
            }
            CPCOMMIT;
        }
        __half* As = dynsm + sCur * SLOT;
        __half* Bs = dynsm + 3 * SLOT + sCur * SLOT;
        #pragma unroll
        for (int s = 0; s < 2; s++) {
            FragA af[2];
            FragBc bf[4];
            #pragma unroll
            for (int ii = 0; ii < 2; ii++)
                wmma::load_matrix_sync(af[ii], &As[(mw + ii * 16) * LDH + s * 16], LDH);
            #pragma unroll
            for (int j = 0; j < 4; j++)
                wmma::load_matrix_sync(bf[j], &Bs[(nw + j * 16) * LDH + s * 16], LDH);
            #pragma unroll
            for (int ii = 0; ii < 2; ii++)
                #pragma unroll
                for (int j = 0; j < 4; j++)
                    wmma::mma_sync(acc[ii][j], af[ii], bf[j], acc[ii][j]);
        }
        sCur = (sCur == 2) ? 0 : sCur + 1;
    }
    __syncthreads();   // protect staging region from lagging warps
    float sc = scale_z ? scale_z[z] : 1.f;
    float* stage = reinterpret_cast<float*>(dynsm) + wid * 320;   // 16x20 fp32 per warp
    const int er = lane >> 1, ec0 = (lane & 1) * 8;
    #pragma unroll
    for (int i = 0; i < 2; i++) {
        #pragma unroll
        for (int j = 0; j < 4; j++) {
            wmma::store_matrix_sync(stage, acc[i][j], 20, wmma::mem_row_major);
            __syncwarp();
            int row = m0 + mw + i * 16 + er;
            int col = n0 + nw + j * 16 + ec0;
            float vals[8];
            #pragma unroll
            for (int q = 0; q < 8; q++) {
                float v = stage[er * 20 + ec0 + q] * sc;
                int nn = col + q;
                if (bias)   v += bias[nn];
                if (addsrc) v += addsrc[(long long)row * ldadd + nn];
                if (act)    v = v / (1.f + __expf(-v));
                vals[q] = v;
            }
            if (out_half) {
                __half2* cp = reinterpret_cast<__half2*>(
                    (__half*)Cv + z1 * sC1 + z2 * sC2 + (long long)row * ldc + col);
                cp[0] = __floats2half2_rn(vals[0], vals[1]);
                cp[1] = __floats2half2_rn(vals[2], vals[3]);
                cp[2] = __floats2half2_rn(vals[4], vals[5]);
                cp[3] = __floats2half2_rn(vals[6], vals[7]);
            } else {
                float* cf = (float*)Cv + z1 * sC1 + z2 * sC2 + (long long)row * ldc + col;
                *reinterpret_cast<float4*>(cf)     = make_float4(vals[0], vals[1], vals[2], vals[3]);
                *reinterpret_cast<float4*>(cf + 4) = make_float4(vals[4], vals[5], vals[6], vals[7]);
            }
            __syncwarp();
        }
    }
}

// ========== C = A @ B (row-major B, N=64), silu epilogue (AV), fp16 ==========
__global__ __launch_bounds__(256) void k_gemm_ab_silu(
    const __half* __restrict__ A, int lda, long long sA1, long long sA2,
    const __half* __restrict__ B, int ldb, long long sB1, long long sB2,
    __half* __restrict__ C, int ldc, long long sC1, long long sC2,
    int K, int zdiv)
{
    extern __shared__ __half dynsm[];
    int z = blockIdx.z, z1 = z / zdiv, z2 = z % zdiv;
    A += z1 * sA1 + z2 * sA2;
    B += z1 * sB1 + z2 * sB2;
    C += z1 * sC1 + z2 * sC2;
    const int m0 = blockIdx.x * 128;
    const int tid = threadIdx.x, wid = tid >> 5, lane = tid & 31;
    const int mw = (wid >> 1) * 32, nw = (wid & 1) * 32;
    const int lr = tid >> 1, ls = tid & 1;
    const int vr = tid >> 3, vseg = tid & 7;   // tid<256: 32 rows x 8 segs
    __half* Vbase = dynsm + 3 * SLOT;

    FragC acc[2][2];
    #pragma unroll
    for (int i = 0; i < 2; i++)
        #pragma unroll
        for (int j = 0; j < 2; j++) wmma::fill_fragment(acc[i][j], 0.f);

    const int nIter = K / KT;
    #pragma unroll
    for (int p = 0; p < 2; p++) {
        if (p < nIter) {
            int k0 = p * KT;
            __half* As = dynsm + p * SLOT;
            __half* Vs = Vbase + p * VSLOT;
            #pragma unroll
            for (int rep = 0; rep < 2; rep++) {
                int seg = ls + rep * 2;
                cp16(&As[lr * LDH + seg * 8], &A[(long long)(m0 + lr) * lda + k0 + seg * 8]);
            }
            cp16(&Vs[vr * VLD + vseg * 8], &B[(long long)(k0 + vr) * ldb + vseg * 8]);
            CPCOMMIT;
        }
    }
    int sCur = 0;
    for (int i = 0; i < nIter; i++) {
        if (i + 1 < nIter) { CPWAIT1; } else { CPWAIT0; }
        __syncthreads();
        if (i + 2 < nIter) {
            int sPre = sCur + 2; if (sPre >= 3) sPre -= 3;
            int k0 = (i + 2) * KT;
            __half* As = dynsm + sPre * SLOT;
            __half* Vs = Vbase + sPre * VSLOT;
            #pragma unroll
            for (int rep = 0; rep < 2; rep++) {
                int seg = ls + rep * 2;
                cp16(&As[lr * LDH + seg * 8], &A[(long long)(m0 + lr) * lda + k0 + seg * 8]);
            }
            cp16(&Vs[vr * VLD + vseg * 8], &B[(long long)(k0 + vr) * ldb + vseg * 8]);
            CPCOMMIT;
        }
        __half* As = dynsm + sCur * SLOT;
        __half* Vs = Vbase + sCur * VSLOT;
        #pragma unroll
        for (int s = 0; s < 2; s++) {
            FragA af[2];
            FragBr bf[2];
            #pragma unroll
            for (int ii = 0; ii < 2; ii++)
                wmma::load_matrix_sync(af[ii], &As[(mw + ii * 16) * LDH + s * 16], LDH);
            #pragma unroll
            for (int j = 0; j < 2; j++)
                wmma::load_matrix_sync(bf[j], &Vs[(s * 16) * VLD + nw + j * 16], VLD);
            #pragma unroll
            for (int ii = 0; ii < 2; ii++)
                #pragma unroll
                for (int j = 0; j < 2; j++)
                    wmma::mma_sync(acc[ii][j], af[ii], bf[j], acc[ii][j]);
        }
        sCur = (sCur == 2) ? 0 : sCur + 1;
    }
    __syncthreads();
    float* stage = reinterpret_cast<float*>(dynsm) + wid * 320;
    const int er = lane >> 1, ec0 = (lane & 1) * 8;
    #pragma unroll
    for (int i = 0; i < 2; i++) {
        #pragma unroll
        for (int j = 0; j < 2; j++) {
            wmma::store_matrix_sync(stage, acc[i][j], 20, wmma::mem_row_major);
            __syncwarp();
            int row = m0 + mw + i * 16 + er;
            int col = nw + j * 16 + ec0;
            float vals[8];
            #pragma unroll
            for (int q = 0; q < 8; q++) {
                float v = stage[er * 20 + ec0 + q];
                vals[q] = v / (1.f + __expf(-v));
            }
            __half2* cp = reinterpret_cast<__half2*>(&C[(long long)row * ldc + col]);
            cp[0] = __floats2half2_rn(vals[0], vals[1]);
            cp[1] = __floats2half2_rn(vals[2], vals[3]);
            cp[2] = __floats2half2_rn(vals[4], vals[5]);
            cp[3] = __floats2half2_rn(vals[6], vals[7]);
            __syncwarp();
        }
    }
}

// ---------------- small kernels ----------------
__global__ void k_colmean_f(const float* __restrict__ x, int lda) {
    int b = blockIdx.y;
    int c = blockIdx.x * 256 + threadIdx.x;
    const float* p = x + (long long)b * Tt * lda + c;
    float s = 0.f;
    for (int t = 0; t < Tt; t++) s += p[(long long)t * lda];
    g_mean[b * Cc + c] = s * (1.f / Tt);
}
__global__ void k_colmean_h(const __half* __restrict__ x, int lda) {
    int b = blockIdx.y;
    int c = blockIdx.x * 256 + threadIdx.x;
    const __half* p = x + (long long)b * Tt * lda + c;
    float s = 0.f;
    for (int t = 0; t < Tt; t++) s += __half2float(p[(long long)t * lda]);
    g_mean[b * Cc + c] = s * (1.f / Tt);
}

__global__ void k_aware(const float* __restrict__ aw, const float* __restrict__ ab,
                        const float* __restrict__ ds) {
    int b = blockIdx.x >> 4, h = blockIdx.x & 15;
    const float* m = g_mean + b * Cc;
    const float* w = aw + h * Cc;
    float s = 0.f;
    for (int c = threadIdx.x; c < Cc; c += 256) s += m[c] * w[c];
    s = blockReduceSum(s);
    if (threadIdx.x == 0) g_scale[b * Hh + h] = ds[0] * (s + ab[h]);
}

__global__ void k_softmax_prior(int phase) {
    long long row = blockIdx.x;
    const __half* s = g_scores + row * Tt;
    __half* a = g_attn + row * Tt;
    int tid = threadIdx.x;
    float v[4];
    float mx = -1e30f;
    #pragma unroll
    for (int i = 0; i < 4; i++) { v[i] = __half2float(s[tid + i * 256]); mx = fmaxf(mx, v[i]); }
    mx = blockReduceMax(mx);
    float sum = 0.f;
    #pragma unroll
    for (int i = 0; i < 4; i++) { v[i] = __expf(v[i] - mx); sum += v[i]; }
    sum = blockReduceSum(sum);
    float inv = 1.f / sum;
    #pragma unroll
    for (int i = 0; i < 4; i++) {
        float o = v[i] * inv;
        if (phase) o += 0.3f * __half2float(a[tid + i * 256]);
        a[tid + i * 256] = __float2half_rn(o);
    }
}

__global__ void k_layernorm(const float* __restrict__ gam, const float* __restrict__ bet,
                            float* __restrict__ out) {
    int row = blockIdx.x;
    const float* y = g_y + (long long)row * Cc;
    float s = 0.f, q = 0.f;
    for (int c = threadIdx.x; c < Cc; c += 256) { float v = y[c]; s += v; q += v * v; }
    s = blockReduceSum(s);
    q = blockReduceSum(q);
    float mu = s * (1.f / Cc);
    float var = q * (1.f / Cc) - mu * mu;
    float inv = rsqrtf(var + 1e-5f);
    for (int c = threadIdx.x; c < Cc; c += 256) {
        float xn = (y[c] - mu) * inv * gam[c] + bet[c];
        g_xn[(long long)row * Cc + c] = __float2half_rn(xn);   // half copy for GEMM input
        out[(long long)row * Cc + c] = xn;                     // exact output
    }
}

__global__ void k_zero() { if (threadIdx.x < Ee) g_cursor[threadIdx.x] = 0; }

__global__ void k_gate(const float* __restrict__ gw) {
    int n = blockIdx.x;
    int wid = threadIdx.x >> 5, lane = threadIdx.x & 31;
    __shared__ float lg[Ee];
    const __half* t = g_xn + (long long)n * Cc;
    const float* w = gw + wid * Cc;
    float s = 0.f;
    for (int c = lane; c < Cc; c += 32) s += __half2float(t[c]) * w[c];
    #pragma unroll
    for (int o = 16; o; o >>= 1) s += __shfl_xor_sync(0xffffffffu, s, o);
    if (lane == 0) lg[wid] = s;
    __syncthreads();
    if (threadIdx.x == 0) {
        float mx = lg[0];
        #pragma unroll
        for (int e = 1; e < Ee; e++) mx = fmaxf(mx, lg[e]);
        float p[Ee];
        #pragma unroll
        for (int e = 0; e < Ee; e++) p[e] = __expf(lg[e] - mx);
        int i1 = 0;
        #pragma unroll
        for (int e = 1; e < Ee; e++) if (p[e] > p[i1]) i1 = e;
        int i2 = (i1 == 0) ? 1 : 0;
        #pragma unroll
        for (int e = 0; e < Ee; e++) if (e != i1 && p[e] > p[i2]) i2 = e;
        float tot = p[i1] + p[i2];
        float w1 = p[i1] / tot, w2 = p[i2] / tot;
        int p1 = atomicAdd(&g_cursor[i1], 1);
        g_tok[i1 * NN + p1] = n; g_wgt[i1 * NN + p1] = w1;
        int p2 = atomicAdd(&g_cursor[i2], 1);
        g_tok[i2 * NN + p2] = n; g_wgt[i2 * NN + p2] = w2;
    }
}

// ========== gathered expert FC1, fp16 wmma, 3-stage, a = h^2*sigmoid(h) ==========
__global__ __launch_bounds__(256) void k_fc1(const __half* __restrict__ fc1w,
                                             const float* __restrict__ fc1b) {
    extern __shared__ __half dynsm[];
    int e = blockIdx.z;
    int cnt = g_cursor[e];
    int m0 = blockIdx.x * 128;
    if (m0 >= cnt) return;
    int n0 = blockIdx.y * 128;
    const __half* Bw = fc1w + (long long)e * DFF * Cc;
    __shared__ int toks[128];
    const int tid = threadIdx.x, wid = tid >> 5, lane = tid & 31;
    const int mw = (wid >> 1) * 32, nw = (wid & 1) * 64;
    const int lr = tid >> 1, ls = tid & 1;
    if (tid < 128) {
        int m = m0 + tid;
        toks[tid] = (m < cnt) ? g_tok[e * NN + m] : -1;
    }
    __syncthreads();
    FragC acc[2][4];
    #pragma unroll
    for (int i = 0; i < 2; i++)
        #pragma unroll
        for (int j = 0; j < 4; j++) wmma::fill_fragment(acc[i][j], 0.f);

    const int nIter = Cc / KT;
    const int tk0 = toks[lr];
    #pragma unroll
    for (int p = 0; p < 2; p++) {
        int k0 = p * KT;
        __half* As = dynsm + p * SLOT;
        __half* Bs = dynsm + 3 * SLOT + p * SLOT;
        #pragma unroll
        for (int rep = 0; rep < 2; rep++) {
            int seg = ls + rep * 2;
            cp16p(&As[lr * LDH + seg * 8],
                  &g_xn[(long long)(tk0 < 0 ? 0 : tk0) * Cc + k0 + seg * 8], tk0 >= 0);
            cp16(&Bs[lr * LDH + seg * 8], &Bw[(long long)(n0 + lr) * Cc + k0 + seg * 8]);
        }
        CPCOMMIT;
    }
    int sCur = 0;
    for (int i = 0; i < nIter; i++) {
        if (i + 1 < nIter) { CPWAIT1; } else { CPWAIT0; }
        __syncthreads();
        if (i + 2 < nIter) {
            int sPre = sCur + 2; if (sPre >= 3) sPre -= 3;
            int k0 = (i + 2) * KT;
            __half* As = dynsm + sPre * SLOT;
            __half* Bs = dynsm + 3 * SLOT + sPre * SLOT;
            #pragma unroll
            for (int rep = 0; rep < 2; rep++) {
                int seg = ls + rep * 2;
                cp16p(&As[lr * LDH + seg * 8],
                      &g_xn[(long long)(tk0 < 0 ? 0 : tk0) * Cc + k0 + seg * 8], tk0 >= 0);
                cp16(&Bs[lr * LDH + seg * 8], &Bw[(long long)(n0 + lr) * Cc + k0 + seg * 8]);
            }
            CPCOMMIT;
        }
        __half* As = dynsm + sCur * SLOT;
        __half* Bs = dynsm + 3 * SLOT + sCur * SLOT;
        #pragma unroll
        for (int s = 0; s < 2; s++) {
            FragA af[2];
            FragBc bf[4];
            #pragma unroll
            for (int ii = 0; ii < 2; ii++)
                wmma::load_matrix_sync(af[ii], &As[(mw + ii * 16) * LDH + s * 16], LDH);
            #pragma unroll
            for (int j = 0; j < 4; j++)
                wmma::load_matrix_sync(bf[j], &Bs[(nw + j * 16) * LDH + s * 16], LDH);
            #pragma unroll
            for (int ii = 0; ii < 2; ii++)
                #pragma unroll
                for (int j = 0; j < 4; j++)
                    wmma::mma_sync(acc[ii][j], af[ii], bf[j], acc[ii][j]);
        }
        sCur = (sCur == 2) ? 0 : sCur + 1;
    }
    __syncthreads();
    const float* bp = fc1b + e * DFF;
    float* stage = reinterpret_cast<float*>(dynsm) + wid * 320;
    const int er = lane >> 1, ec0 = (lane & 1) * 8;
    #pragma unroll
    for (int i = 0; i < 2; i++) {
        #pragma unroll
        for (int j = 0; j < 4; j++) {
            wmma::store_matrix_sync(stage, acc[i][j], 20, wmma::mem_row_major);
            __syncwarp();
            int m = m0 + mw + i * 16 + er;
            if (m < cnt) {
                int n = n0 + nw + j * 16 + ec0;
                float vals[8];
                #pragma unroll
                for (int q = 0; q < 8; q++) {
                    float h = stage[er * 20 + ec0 + q] + bp[n + q];
                    vals[q] = h * h / (1.f + __expf(-h));   // h * silu(h)
                }
                __half2* op = reinterpret_cast<__half2*>(&g_act[((long long)e * NN + m) * DFF + n]);
                op[0] = __floats2half2_rn(vals[0], vals[1]);
                op[1] = __floats2half2_rn(vals[2], vals[3]);
                op[2] = __floats2half2_rn(vals[4], vals[5]);
                op[3] = __floats2half2_rn(vals[6], vals[7]);
            }
            __syncwarp();
        }
    }
}

// ========== gathered expert FC2 + weighted scatter-add, fp16 wmma, 3-stage ==========
__global__ __launch_bounds__(256) void k_fc2(const __half* __restrict__ fc2w,
                                             const float* __restrict__ fc2b,
                                             float* __restrict__ out) {
    extern __shared__ __half dynsm[];
    int e = blockIdx.z;
    int cnt = g_cursor[e];
    int m0 = blockIdx.x * 128;
    if (m0 >= cnt) return;
    int n0 = blockIdx.y * 128;
    const __half* Aa = g_act + (long long)e * NN * DFF;
    const __half* Bw = fc2w + (long long)e * Cc * DFF;
    const int tid = threadIdx.x, wid = tid >> 5, lane = tid & 31;
    const int mw = (wid >> 1) * 32, nw = (wid & 1) * 64;
    const int lr = tid >> 1, ls = tid & 1;
    FragC acc[2][4];
    #pragma unroll
    for (int i = 0; i < 2; i++)
        #pragma unroll
        for (int j = 0; j < 4; j++) wmma::fill_fragment(acc[i][j], 0.f);

    const int nIter = DFF / KT;
    const bool mok = (m0 + lr) < cnt;
    #pragma unroll
    for (int p = 0; p < 2; p++) {
        int k0 = p * KT;
        __half* As = dynsm + p * SLOT;
        __half* Bs = dynsm + 3 * SLOT + p * SLOT;
        #pragma unroll
        for (int rep = 0; rep < 2; rep++) {
            int seg = ls + rep * 2;
            cp16p(&As[lr * LDH + seg * 8], &Aa[(long long)(m0 + lr) * DFF + k0 + seg * 8], mok);
            cp16(&Bs[lr * LDH + seg * 8], &Bw[(long long)(n0 + lr) * DFF + k0 + seg * 8]);
        }
        CPCOMMIT;
    }
    int sCur = 0;
    for (int i = 0; i < nIter; i++) {
        if (i + 1 < nIter) { CPWAIT1; } else { CPWAIT0; }
        __syncthreads();
        if (i + 2 < nIter) {
            int sPre = sCur + 2; if (sPre >= 3) sPre -= 3;
            int k0 = (i + 2) * KT;
            __half* As = dynsm + sPre * SLOT;
            __half* Bs = dynsm + 3 * SLOT + sPre * SLOT;
            #pragma unroll
            for (int rep = 0; rep < 2; rep++) {
                int seg = ls + rep * 2;
                cp16p(&As[lr * LDH + seg * 8], &Aa[(long long)(m0 + lr) * DFF + k0 + seg * 8], mok);
                cp16(&Bs[lr * LDH + seg * 8], &Bw[(long long)(n0 + lr) * DFF + k0 + seg * 8]);
            }
            CPCOMMIT;
        }
        __half* As = dynsm + sCur * SLOT;
        __half* Bs = dynsm + 3 * SLOT + sCur * SLOT;
        #pragma unroll
        for (int s = 0; s < 2; s++) {
            FragA af[2];
            FragBc bf[4];
            #pragma unroll
            for (int ii = 0; ii < 2; ii++)
                wmma::load_matrix_sync(af[ii], &As[(mw + ii * 16) * LDH + s * 16], LDH);
            #pragma unroll
            for (int j = 0; j < 4; j++)
                wmma::load_matrix_sync(bf[j], &Bs[(nw + j * 16) * LDH + s * 16], LDH);
            #pragma unroll
            for (int ii = 0; ii < 2; ii++)
                #pragma unroll
                for (int j = 0; j < 4; j++)
                    wmma::mma_sync(acc[ii][j], af[ii], bf[j], acc[ii][j]);
        }
        sCur = (sCur == 2) ? 0 : sCur + 1;
    }
    __syncthreads();
    const float* bp = fc2b + e * Cc;
    float* stage = reinterpret_cast<float*>(dynsm) + wid * 320;
    const int er = lane >> 1, ec0 = (lane & 1) * 8;
    #pragma unroll
    for (int i = 0; i < 2; i++) {
        #pragma unroll
        for (int j = 0; j < 4; j++) {
            wmma::store_matrix_sync(stage, acc[i][j], 20, wmma::mem_row_major);
            __syncwarp();
            int m = m0 + mw + i * 16 + er;
            if (m < cnt) {
                int tk = g_tok[e * NN + m];
                float w = g_wgt[e * NN + m] * 0.5f;   // * RATIO
                int n = n0 + nw + j * 16 + ec0;
                #pragma unroll
                for (int q = 0; q < 8; q++) {
                    atomicAdd(&out[(long long)tk * Cc + n + q],
                              (stage[er * 20 + ec0 + q] + bp[n + q]) * w);
                }
            }
            __syncwarp();
        }
    }
}

// ---------------- launch ----------------
extern "C" void kernel_launch(void* const* d_in, const int* in_sizes, int n_in,
                              void* d_out, int out_size) {
    (void)in_sizes; (void)n_in; (void)out_size;
    const float* x       = (const float*)d_in[0];
    const float* qkv_w   = (const float*)d_in[1];
    const float* qkv_b   = (const float*)d_in[2];
    const float* aware_w = (const float*)d_in[3];
    const float* aware_b = (const float*)d_in[4];
    const float* dyn     = (const float*)d_in[5];
    const float* mw      = (const float*)d_in[6];
    const float* mb      = (const float*)d_in[7];
    const float* lng     = (const float*)d_in[8];
    const float* lnb     = (const float*)d_in[9];
    const float* gw      = (const float*)d_in[10];
    const float* f1w     = (const float*)d_in[11];
    const float* f1b     = (const float*)d_in[12];
    const float* f2w     = (const float*)d_in[13];
    const float* f2b     = (const float*)d_in[14];
    float* out = (float*)d_out;

    cudaFuncSetAttribute(k_gemm_abT,     cudaFuncAttributeMaxDynamicSharedMemorySize, SMEM_ABT);
    cudaFuncSetAttribute(k_gemm_ab_silu, cudaFuncAttributeMaxDynamicSharedMemorySize, SMEM_AV);
    cudaFuncSetAttribute(k_fc1,          cudaFuncAttributeMaxDynamicSharedMemorySize, SMEM_ABT);
    cudaFuncSetAttribute(k_fc2,          cudaFuncAttributeMaxDynamicSharedMemorySize, SMEM_ABT);

    __half *catp, *qkvp, *scoresp, *attnp, *xnp;
    float *yp, *scalep;
    __half *rxp, *rqwp, *rmwp, *rf1p, *rf2p;
    cudaGetSymbolAddress((void**)&catp,    g_cat);
    cudaGetSymbolAddress((void**)&qkvp,    g_qkv);
    cudaGetSymbolAddress((void**)&scoresp, g_scores);
    cudaGetSymbolAddress((void**)&attnp,   g_attn);
    cudaGetSymbolAddress((void**)&xnp,     g_xn);
    cudaGetSymbolAddress((void**)&yp,      g_y);
    cudaGetSymbolAddress((void**)&scalep,  g_scale);
    cudaGetSymbolAddress((void**)&rxp,     r_x);
    cudaGetSymbolAddress((void**)&rqwp,    r_qkvw);
    cudaGetSymbolAddress((void**)&rmwp,    r_mw);
    cudaGetSymbolAddress((void**)&rf1p,    r_f1w);
    cudaGetSymbolAddress((void**)&rf2p,    r_f2w);

    // float -> half conversion of all harness-provided GEMM operands
    k_cvt<<<1024, 256>>>((const float4*)x,     (uint2*)rxp,  NN*Cc/4);
    k_cvt<<<2048, 256>>>((const float4*)qkv_w, (uint2*)rqwp, Pp*C3*Cc/4);
    k_cvt<<<1024, 256>>>((const float4*)mw,    (uint2*)rmwp, Cc*C3/4);
    k_cvt<<<2048, 256>>>((const float4*)f1w,   (uint2*)rf1p, Ee*DFF*Cc/4);
    k_cvt<<<2048, 256>>>((const float4*)f2w,   (uint2*)rf2p, Ee*Cc*DFF/4);

    for (int i = 0; i < Pp; i++) {
        const __half* xin = (i == 0) ? rxp : (catp + (i - 1) * Cc);
        int ldx = (i == 0) ? Cc : C3;

        if (i == 0) k_colmean_f<<<dim3(Cc / 256, Bb), 256>>>(x, Cc);
        else        k_colmean_h<<<dim3(Cc / 256, Bb), 256>>>(catp + (i - 1) * Cc, C3);
        k_aware<<<Bb * Hh, 256>>>(aware_w + (long long)i * Hh * Cc,
                                  aware_b + i * Hh, dyn + i);
        // qkv: (2048 x 1024) @ (3072 x 1024)^T + b -> g_qkv (half)
        k_gemm_abT<<<dim3(NN / 128, C3 / 128, 1), 256, SMEM_ABT>>>(
            xin, ldx, 0, 0,
            rqwp + (long long)i * C3 * Cc, Cc, 0, 0,
            qkv_b + (long long)i * C3,
            qkvp, C3, 0, 0,
            Cc, 1, nullptr, nullptr, 0, 0, 1);
        // scores: per (b,h): Q(1024x64) @ K^T, scaled -> g_scores (half)
        k_gemm_abT<<<dim3(Tt / 128, Tt / 128, Bb * Hh), 256, SMEM_ABT>>>(
            qkvp,       C3, (long long)Tt * C3, Dd,
            qkvp + Cc,  C3, (long long)Tt * C3, Dd,
            nullptr,
            scoresp, Tt, (long long)Hh * Tt * Tt, (long long)Tt * Tt,
            Dd, Hh, scalep, nullptr, 0, 0, 1);
        // softmax + prior recurrence (half in/out)
        k_softmax_prior<<<Bb * Hh * Tt, 256>>>(i);
        // AV: attn(1024x1024) @ V(1024x64), silu -> g_cat[:, i*C ...] (half)
        k_gemm_ab_silu<<<dim3(Tt / 128, 1, Bb * Hh), 256, SMEM_AV>>>(
            attnp,          Tt, (long long)Hh * Tt * Tt, (long long)Tt * Tt,
            qkvp + 2 * Cc,  C3, (long long)Tt * C3, Dd,
            catp + i * Cc,  C3, (long long)Tt * C3, Dd,
            Tt, Hh);
    }

    // merger: (2048 x 3072) @ (1024 x 3072)^T + b + residual(exact x) -> g_y (float)
    k_gemm_abT<<<dim3(NN / 128, Cc / 128, 1), 256, SMEM_ABT>>>(
        catp, C3, 0, 0,
        rmwp, C3, 0, 0,
        mb,
        yp, Cc, 0, 0,
        C3, 1, nullptr, x, Cc, 0, 0);

    k_layernorm<<<NN, 256>>>(lng, lnb, out);   // g_xn half copy, d_out exact
    k_zero<<<1, 32>>>();
    k_gate<<<NN, 256>>>(gw);
    k_fc1<<<dim3(NN / 128, DFF / 128, Ee), 256, SMEM_ABT>>>(rf1p, f1b);
    k_fc2<<<dim3(NN / 128, Cc / 128, Ee), 256, SMEM_ABT>>>(rf2p, f2b, out);
}

// round 13
// speedup vs baseline: 2.2613x; 1.1518x over previous
#include <cuda_runtime.h>
#include <cuda_fp16.h>
#include <mma.h>
using namespace nvcuda;

#define Bb   2
#define Tt   1024
#define Cc   1024
#define Hh   16
#define Dd   64
#define Pp   3
#define Ee   8
#define DFF  1024
#define NN   (Bb*Tt)          // 2048 tokens
#define C3   (3*Cc)           // 3072

// ---------------- scratch (static device allocations) ----------------
__device__ __half g_qkv[NN*C3];
__device__ __half g_cat[NN*C3];
__device__ __half g_scores[Bb*Hh*Tt*Tt];
__device__ __half g_attn[Bb*Hh*Tt*Tt];
__device__ float  g_y[NN*Cc];
__device__ __half g_xn[NN*Cc];          // half copy for GEMM/gate inputs
__device__ float  g_mean[Bb*Cc];
__device__ float  g_scale[Bb*Hh];
__device__ int    g_cursor[Ee];
__device__ int    g_tok[Ee*NN];
__device__ float  g_wgt[Ee*NN];
__device__ __half g_act[Ee*NN*DFF];
// half copies of harness inputs (converted once per launch)
__device__ __half r_x[NN*Cc];
__device__ __half r_qkvw[Pp*C3*Cc];
__device__ __half r_mw[Cc*C3];
__device__ __half r_f1w[Ee*DFF*Cc];
__device__ __half r_f2w[Ee*Cc*DFF];

typedef wmma::fragment<wmma::matrix_a, 16, 16, 16, __half, wmma::row_major> FragA;
typedef wmma::fragment<wmma::matrix_b, 16, 16, 16, __half, wmma::col_major> FragBc;
typedef wmma::fragment<wmma::matrix_b, 16, 16, 16, __half, wmma::row_major> FragBr;
typedef wmma::fragment<wmma::accumulator, 16, 16, 16, float> FragC;

// ---------------- cp.async helpers ----------------
__device__ __forceinline__ void cp16(void* dst, const void* src) {
    unsigned ds = (unsigned)__cvta_generic_to_shared(dst);
    asm volatile("cp.async.cg.shared.global [%0], [%1], 16;" :: "r"(ds), "l"(src));
}
__device__ __forceinline__ void cp16p(void* dst, const void* src, bool pred) {
    unsigned ds = (unsigned)__cvta_generic_to_shared(dst);
    int sz = pred ? 16 : 0;
    asm volatile("cp.async.cg.shared.global [%0], [%1], 16, %2;" :: "r"(ds), "l"(src), "r"(sz));
}
#define CPCOMMIT asm volatile("cp.async.commit_group;")
#define CPWAIT0  asm volatile("cp.async.wait_group 0;")
#define CPWAIT1  asm volatile("cp.async.wait_group 1;")

#define KT   64                   // k-tile depth (halves)
#define LDH  72                   // row stride in halves (64 + 8 pad)
#define SLOT (128*LDH)            // 9216 halves per tile slot
#define SMEM_ABT (6*SLOT*2)       // 110592 B: 3 A slots + 3 B slots
#define VLD  72
#define VSLOT (64*VLD)            // 4608 halves
#define SMEM_AV ((3*SLOT + 3*VSLOT)*2)   // 82944 B

// ---------------- block reductions (8 warps) ----------------
__device__ __forceinline__ float blockReduceSum(float v) {
    __shared__ float sh[8];
    int lane = threadIdx.x & 31, w = threadIdx.x >> 5;
    #pragma unroll
    for (int o = 16; o; o >>= 1) v += __shfl_xor_sync(0xffffffffu, v, o);
    if (lane == 0) sh[w] = v;
    __syncthreads();
    float r = 0.f;
    #pragma unroll
    for (int i = 0; i < 8; i++) r += sh[i];
    __syncthreads();
    return r;
}
__device__ __forceinline__ float blockReduceMax(float v) {
    __shared__ float sh[8];
    int lane = threadIdx.x & 31, w = threadIdx.x >> 5;
    #pragma unroll
    for (int o = 16; o; o >>= 1) v = fmaxf(v, __shfl_xor_sync(0xffffffffu, v, o));
    if (lane == 0) sh[w] = v;
    __syncthreads();
    float r = -1e30f;
    #pragma unroll
    for (int i = 0; i < 8; i++) r = fmaxf(r, sh[i]);
    __syncthreads();
    return r;
}

// ---------------- float -> half convert (float4 -> 4 halves) ----------------
__global__ void k_cvt(const float4* __restrict__ src, uint2* __restrict__ dst, int n4) {
    for (int i = blockIdx.x * blockDim.x + threadIdx.x; i < n4; i += gridDim.x * blockDim.x) {
        float4 t = src[i];
        __half2 h0 = __floats2half2_rn(t.x, t.y);
        __half2 h1 = __floats2half2_rn(t.z, t.w);
        uint2 o;
        o.x = *reinterpret_cast<unsigned*>(&h0);
        o.y = *reinterpret_cast<unsigned*>(&h1);
        dst[i] = o;
    }
}

// ========== generic C = A @ B^T, 128x128 tiles, fp16 wmma, 3-stage cp.async ==========
__global__ __launch_bounds__(256) void k_gemm_abT(
    const __half* __restrict__ A, int lda, long long sA1, long long sA2,
    const __half* __restrict__ B, int ldb, long long sB1, long long sB2,
    const float* __restrict__ bias,
    void* __restrict__ Cv, int ldc, long long sC1, long long sC2,
    int K, int zdiv,
    const float* __restrict__ scale_z,
    const float* __restrict__ addsrc, int ldadd,
    int act, int out_half)
{
    extern __shared__ __half dynsm[];
    int z = blockIdx.z, z1 = z / zdiv, z2 = z % zdiv;
    A += z1 * sA1 + z2 * sA2;
    B += z1 * sB1 + z2 * sB2;
    const int m0 = blockIdx.x * 128, n0 = blockIdx.y * 128;
    const int tid = threadIdx.x, wid = tid >> 5, lane = tid & 31;
    const int mw = (wid >> 1) * 32, nw = (wid & 1) * 64;

    FragC acc[2][4];
    #pragma unroll
    for (int i = 0; i < 2; i++)
        #pragma unroll
        for (int j = 0; j < 4; j++) wmma::fill_fragment(acc[i][j], 0.f);

    const int nIter = K / KT;
    #pragma unroll
    for (int p = 0; p < 2; p++) {
        if (p < nIter) {
            int k0 = p * KT;
            __half* As = dynsm + p * SLOT;
            __half* Bs = dynsm + 3 * SLOT + p * SLOT;
            #pragma unroll
            for (int rep = 0; rep < 4; rep++) {
                int v = rep * 256 + tid, r = v >> 3, seg = v & 7;
                cp16(&As[r * LDH + seg * 8], &A[(long long)(m0 + r) * lda + k0 + seg * 8]);
                cp16(&Bs[r * LDH + seg * 8], &B[(long long)(n0 + r) * ldb + k0 + seg * 8]);
            }
            CPCOMMIT;
        }
    }
    int sCur = 0;
    for (int i = 0; i < nIter; i++) {
        if (i + 1 < nIter) { CPWAIT1; } else { CPWAIT0; }
        __syncthreads();
        if (i + 2 < nIter) {
            int sPre = sCur + 2; if (sPre >= 3) sPre -= 3;
            int k0 = (i + 2) * KT;
            __half* As = dynsm + sPre * SLOT;
            __half* Bs = dynsm + 3 * SLOT + sPre * SLOT;
            #pragma unroll
            for (int rep = 0; rep < 4; rep++) {
                int v = rep * 256 + tid, r = v >> 3, seg = v & 7;
                cp16(&As[r * LDH + seg * 8], &A[(long long)(m0 + r) * lda + k0 + seg * 8]);
                cp16(&Bs[r * LDH + seg * 8], &B[(long long)(n0 + r) * ldb + k0 + seg * 8]);
            }
            CPCOMMIT;
        }
        __half* As = dynsm + sCur * SLOT;
        __half* Bs = dynsm + 3 * SLOT + sCur * SLOT;
        #pragma unroll
        for (int s = 0; s < 4; s++) {
            FragA af[2];
            FragBc bf[4];
            #pragma unroll
            for (int ii = 0; ii < 2; ii++)
                wmma::load_matrix_sync(af[ii], &As[(mw + ii * 16) * LDH + s * 16], LDH);
            #pragma unroll
            for (int j = 0; j < 4; j++)
                wmma::load_matrix_sync(bf[j], &Bs[(nw + j * 16) * LDH + s * 16], LDH);
            #pragma unroll
            for (int ii = 0; ii < 2; ii++)
                #pragma unroll
                for (int j = 0; j < 4; j++)
                    wmma::mma_sync(acc[ii][j], af[ii], bf[j], acc[ii][j]);
        }
        sCur = (sCur == 2) ? 0 : sCur + 1;
    }
    __syncthreads();   // protect staging region from lagging warps
    float sc = scale_z ? scale_z[z] : 1.f;
    float* stage = reinterpret_cast<float*>(dynsm) + wid * 320;   // 16x20 fp32 per warp
    const int er = lane >> 1, ec0 = (lane & 1) * 8;
    #pragma unroll
    for (int i = 0; i < 2; i++) {
        #pragma unroll
        for (int j = 0; j < 4; j++) {
            wmma::store_matrix_sync(stage, acc[i][j], 20, wmma::mem_row_major);
            __syncwarp();
            int row = m0 + mw + i * 16 + er;
            int col = n0 + nw + j * 16 + ec0;
            float vals[8];
            #pragma unroll
            for (int q = 0; q < 8; q++) {
                float v = stage[er * 20 + ec0 + q] * sc;
                int nn = col + q;
                if (bias)   v += bias[nn];
                if (addsrc) v += addsrc[(long long)row * ldadd + nn];
                if (act)    v = v / (1.f + __expf(-v));
                vals[q] = v;
            }
            if (out_half) {
                __half2* cp = reinterpret_cast<__half2*>(
                    (__half*)Cv + z1 * sC1 + z2 * sC2 + (long long)row * ldc + col);
                cp[0] = __floats2half2_rn(vals[0], vals[1]);
                cp[1] = __floats2half2_rn(vals[2], vals[3]);
                cp[2] = __floats2half2_rn(vals[4], vals[5]);
                cp[3] = __floats2half2_rn(vals[6], vals[7]);
            } else {
                float* cf = (float*)Cv + z1 * sC1 + z2 * sC2 + (long long)row * ldc + col;
                *reinterpret_cast<float4*>(cf)     = make_float4(vals[0], vals[1], vals[2], vals[3]);
                *reinterpret_cast<float4*>(cf + 4) = make_float4(vals[4], vals[5], vals[6], vals[7]);
            }
            __syncwarp();
        }
    }
}

// ========== C = A @ B (row-major B, N=64), silu epilogue (AV), fp16 ==========
__global__ __launch_bounds__(256) void k_gemm_ab_silu(
    const __half* __restrict__ A, int lda, long long sA1, long long sA2,
    const __half* __restrict__ B, int ldb, long long sB1, long long sB2,
    __half* __restrict__ C, int ldc, long long sC1, long long sC2,
    int K, int zdiv)
{
    extern __shared__ __half dynsm[];
    int z = blockIdx.z, z1 = z / zdiv, z2 = z % zdiv;
    A += z1 * sA1 + z2 * sA2;
    B += z1 * sB1 + z2 * sB2;
    C += z1 * sC1 + z2 * sC2;
    const int m0 = blockIdx.x * 128;
    const int tid = threadIdx.x, wid = tid >> 5, lane = tid & 31;
    const int mw = (wid >> 1) * 32, nw = (wid & 1) * 32;
    __half* Vbase = dynsm + 3 * SLOT;

    FragC acc[2][2];
    #pragma unroll
    for (int i = 0; i < 2; i++)
        #pragma unroll
        for (int j = 0; j < 2; j++) wmma::fill_fragment(acc[i][j], 0.f);

    const int nIter = K / KT;
    #pragma unroll
    for (int p = 0; p < 2; p++) {
        if (p < nIter) {
            int k0 = p * KT;
            __half* As = dynsm + p * SLOT;
            __half* Vs = Vbase + p * VSLOT;
            #pragma unroll
            for (int rep = 0; rep < 4; rep++) {
                int v = rep * 256 + tid, r = v >> 3, seg = v & 7;
                cp16(&As[r * LDH + seg * 8], &A[(long long)(m0 + r) * lda + k0 + seg * 8]);
            }
            #pragma unroll
            for (int rep = 0; rep < 2; rep++) {
                int v = rep * 256 + tid, vr = v >> 3, vseg = v & 7;
                cp16(&Vs[vr * VLD + vseg * 8], &B[(long long)(k0 + vr) * ldb + vseg * 8]);
            }
            CPCOMMIT;
        }
    }
    int sCur = 0;
    for (int i = 0; i < nIter; i++) {
        if (i + 1 < nIter) { CPWAIT1; } else { CPWAIT0; }
        __syncthreads();
        if (i + 2 < nIter) {
            int sPre = sCur + 2; if (sPre >= 3) sPre -= 3;
            int k0 = (i + 2) * KT;
            __half* As = dynsm + sPre * SLOT;
            __half* Vs = Vbase + sPre * VSLOT;
            #pragma unroll
            for (int rep = 0; rep < 4; rep++) {
                int v = rep * 256 + tid, r = v >> 3, seg = v & 7;
                cp16(&As[r * LDH + seg * 8], &A[(long long)(m0 + r) * lda + k0 + seg * 8]);
            }
            #pragma unroll
            for (int rep = 0; rep < 2; rep++) {
                int v = rep * 256 + tid, vr = v >> 3, vseg = v & 7;
                cp16(&Vs[vr * VLD + vseg * 8], &B[(long long)(k0 + vr) * ldb + vseg * 8]);
            }
            CPCOMMIT;
        }
        __half* As = dynsm + sCur * SLOT;
        __half* Vs = Vbase + sCur * VSLOT;
        #pragma unroll
        for (int s = 0; s < 4; s++) {
            FragA af[2];
            FragBr bf[2];
            #pragma unroll
            for (int ii = 0; ii < 2; ii++)
                wmma::load_matrix_sync(af[ii], &As[(mw + ii * 16) * LDH + s * 16], LDH);
            #pragma unroll
            for (int j = 0; j < 2; j++)
                wmma::load_matrix_sync(bf[j], &Vs[(s * 16) * VLD + nw + j * 16], VLD);
            #pragma unroll
            for (int ii = 0; ii < 2; ii++)
                #pragma unroll
                for (int j = 0; j < 2; j++)
                    wmma::mma_sync(acc[ii][j], af[ii], bf[j], acc[ii][j]);
        }
        sCur = (sCur == 2) ? 0 : sCur + 1;
    }
    __syncthreads();
    float* stage = reinterpret_cast<float*>(dynsm) + wid * 320;
    const int er = lane >> 1, ec0 = (lane & 1) * 8;
    #pragma unroll
    for (int i = 0; i < 2; i++) {
        #pragma unroll
        for (int j = 0; j < 2; j++) {
            wmma::store_matrix_sync(stage, acc[i][j], 20, wmma::mem_row_major);
            __syncwarp();
            int row = m0 + mw + i * 16 + er;
            int col = nw + j * 16 + ec0;
            float vals[8];
            #pragma unroll
            for (int q = 0; q < 8; q++) {
                float v = stage[er * 20 + ec0 + q];
                vals[q] = v / (1.f + __expf(-v));
            }
            __half2* cp = reinterpret_cast<__half2*>(&C[(long long)row * ldc + col]);
            cp[0] = __floats2half2_rn(vals[0], vals[1]);
            cp[1] = __floats2half2_rn(vals[2], vals[3]);
            cp[2] = __floats2half2_rn(vals[4], vals[5]);
            cp[3] = __floats2half2_rn(vals[6], vals[7]);
            __syncwarp();
        }
    }
}

// ---------------- small kernels ----------------
__global__ void k_colmean_f(const float* __restrict__ x, int lda) {
    int b = blockIdx.y;
    int c = blockIdx.x * 256 + threadIdx.x;
    const float* p = x + (long long)b * Tt * lda + c;
    float s = 0.f;
    for (int t = 0; t < Tt; t++) s += p[(long long)t * lda];
    g_mean[b * Cc + c] = s * (1.f / Tt);
}
__global__ void k_colmean_h(const __half* __restrict__ x, int lda) {
    int b = blockIdx.y;
    int c = blockIdx.x * 256 + threadIdx.x;
    const __half* p = x + (long long)b * Tt * lda + c;
    float s = 0.f;
    for (int t = 0; t < Tt; t++) s += __half2float(p[(long long)t * lda]);
    g_mean[b * Cc + c] = s * (1.f / Tt);
}

__global__ void k_aware(const float* __restrict__ aw, const float* __restrict__ ab,
                        const float* __restrict__ ds) {
    int b = blockIdx.x >> 4, h = blockIdx.x & 15;
    const float* m = g_mean + b * Cc;
    const float* w = aw + h * Cc;
    float s = 0.f;
    for (int c = threadIdx.x; c < Cc; c += 256) s += m[c] * w[c];
    s = blockReduceSum(s);
    if (threadIdx.x == 0) g_scale[b * Hh + h] = ds[0] * (s + ab[h]);
}

// vectorized softmax + prior: 256 threads, uint2 (4 halves) per thread
__global__ void k_softmax_prior(int phase) {
    long long row = blockIdx.x;
    const uint2* s = reinterpret_cast<const uint2*>(g_scores + row * Tt);
    uint2* a = reinterpret_cast<uint2*>(g_attn + row * Tt);
    int tid = threadIdx.x;
    uint2 sv = s[tid];
    __half2 h0 = *reinterpret_cast<__half2*>(&sv.x);
    __half2 h1 = *reinterpret_cast<__half2*>(&sv.y);
    float v[4];
    v[0] = __low2float(h0); v[1] = __high2float(h0);
    v[2] = __low2float(h1); v[3] = __high2float(h1);
    float mx = fmaxf(fmaxf(v[0], v[1]), fmaxf(v[2], v[3]));
    mx = blockReduceMax(mx);
    float sum = 0.f;
    #pragma unroll
    for (int i = 0; i < 4; i++) { v[i] = __expf(v[i] - mx); sum += v[i]; }
    sum = blockReduceSum(sum);
    float inv = 1.f / sum;
    #pragma unroll
    for (int i = 0; i < 4; i++) v[i] *= inv;
    if (phase) {
        uint2 av = a[tid];
        __half2 a0 = *reinterpret_cast<__half2*>(&av.x);
        __half2 a1 = *reinterpret_cast<__half2*>(&av.y);
        v[0] += 0.3f * __low2float(a0); v[1] += 0.3f * __high2float(a0);
        v[2] += 0.3f * __low2float(a1); v[3] += 0.3f * __high2float(a1);
    }
    __half2 o0 = __floats2half2_rn(v[0], v[1]);
    __half2 o1 = __floats2half2_rn(v[2], v[3]);
    uint2 ov;
    ov.x = *reinterpret_cast<unsigned*>(&o0);
    ov.y = *reinterpret_cast<unsigned*>(&o1);
    a[tid] = ov;
}

__global__ void k_layernorm(const float* __restrict__ gam, const float* __restrict__ bet,
                            float* __restrict__ out) {
    int row = blockIdx.x;
    const float* y = g_y + (long long)row * Cc;
    float s = 0.f, q = 0.f;
    for (int c = threadIdx.x; c < Cc; c += 256) { float v = y[c]; s += v; q += v * v; }
    s = blockReduceSum(s);
    q = blockReduceSum(q);
    float mu = s * (1.f / Cc);
    float var = q * (1.f / Cc) - mu * mu;
    float inv = rsqrtf(var + 1e-5f);
    for (int c = threadIdx.x; c < Cc; c += 256) {
        float xn = (y[c] - mu) * inv * gam[c] + bet[c];
        g_xn[(long long)row * Cc + c] = __float2half_rn(xn);   // half copy for GEMM input
        out[(long long)row * Cc + c] = xn;                     // exact output
    }
}

__global__ void k_zero() { if (threadIdx.x < Ee) g_cursor[threadIdx.x] = 0; }

__global__ void k_gate(const float* __restrict__ gw) {
    int n = blockIdx.x;
    int wid = threadIdx.x >> 5, lane = threadIdx.x & 31;
    __shared__ float lg[Ee];
    const __half* t = g_xn + (long long)n * Cc;
    const float* w = gw + wid * Cc;
    float s = 0.f;
    for (int c = lane; c < Cc; c += 32) s += __half2float(t[c]) * w[c];
    #pragma unroll
    for (int o = 16; o; o >>= 1) s += __shfl_xor_sync(0xffffffffu, s, o);
    if (lane == 0) lg[wid] = s;
    __syncthreads();
    if (threadIdx.x == 0) {
        float mx = lg[0];
        #pragma unroll
        for (int e = 1; e < Ee; e++) mx = fmaxf(mx, lg[e]);
        float p[Ee];
        #pragma unroll
        for (int e = 0; e < Ee; e++) p[e] = __expf(lg[e] - mx);
        int i1 = 0;
        #pragma unroll
        for (int e = 1; e < Ee; e++) if (p[e] > p[i1]) i1 = e;
        int i2 = (i1 == 0) ? 1 : 0;
        #pragma unroll
        for (int e = 0; e < Ee; e++) if (e != i1 && p[e] > p[i2]) i2 = e;
        float tot = p[i1] + p[i2];
        float w1 = p[i1] / tot, w2 = p[i2] / tot;
        int p1 = atomicAdd(&g_cursor[i1], 1);
        g_tok[i1 * NN + p1] = n; g_wgt[i1 * NN + p1] = w1;
        int p2 = atomicAdd(&g_cursor[i2], 1);
        g_tok[i2 * NN + p2] = n; g_wgt[i2 * NN + p2] = w2;
    }
}

// ========== gathered expert FC1, fp16 wmma, 3-stage, a = h^2*sigmoid(h) ==========
__global__ __launch_bounds__(256) void k_fc1(const __half* __restrict__ fc1w,
                                             const float* __restrict__ fc1b) {
    extern __shared__ __half dynsm[];
    int e = blockIdx.z;
    int cnt = g_cursor[e];
    int m0 = blockIdx.x * 128;
    if (m0 >= cnt) return;
    int n0 = blockIdx.y * 128;
    const __half* Bw = fc1w + (long long)e * DFF * Cc;
    __shared__ int toks[128];
    const int tid = threadIdx.x, wid = tid >> 5, lane = tid & 31;
    const int mw = (wid >> 1) * 32, nw = (wid & 1) * 64;
    if (tid < 128) {
        int m = m0 + tid;
        toks[tid] = (m < cnt) ? g_tok[e * NN + m] : -1;
    }
    __syncthreads();
    FragC acc[2][4];
    #pragma unroll
    for (int i = 0; i < 2; i++)
        #pragma unroll
        for (int j = 0; j < 4; j++) wmma::fill_fragment(acc[i][j], 0.f);

    const int nIter = Cc / KT;
    #pragma unroll
    for (int p = 0; p < 2; p++) {
        int k0 = p * KT;
        __half* As = dynsm + p * SLOT;
        __half* Bs = dynsm + 3 * SLOT + p * SLOT;
        #pragma unroll
        for (int rep = 0; rep < 4; rep++) {
            int v = rep * 256 + tid, r = v >> 3, seg = v & 7;
            int tk = toks[r];
            cp16p(&As[r * LDH + seg * 8],
                  &g_xn[(long long)(tk < 0 ? 0 : tk) * Cc + k0 + seg * 8], tk >= 0);
            cp16(&Bs[r * LDH + seg * 8], &Bw[(long long)(n0 + r) * Cc + k0 + seg * 8]);
        }
        CPCOMMIT;
    }
    int sCur = 0;
    for (int i = 0; i < nIter; i++) {
        if (i + 1 < nIter) { CPWAIT1; } else { CPWAIT0; }
        __syncthreads();
        if (i + 2 < nIter) {
            int sPre = sCur + 2; if (sPre >= 3) sPre -= 3;
            int k0 = (i + 2) * KT;
            __half* As = dynsm + sPre * SLOT;
            __half* Bs = dynsm + 3 * SLOT + sPre * SLOT;
            #pragma unroll
            for (int rep = 0; rep < 4; rep++) {
                int v = rep * 256 + tid, r = v >> 3, seg = v & 7;
                int tk = toks[r];
                cp16p(&As[r * LDH + seg * 8],
                      &g_xn[(long long)(tk < 0 ? 0 : tk) * Cc + k0 + seg * 8], tk >= 0);
                cp16(&Bs[r * LDH + seg * 8], &Bw[(long long)(n0 + r) * Cc + k0 + seg * 8]);
            }
            CPCOMMIT;
        }
        __half* As = dynsm + sCur * SLOT;
        __half* Bs = dynsm + 3 * SLOT + sCur * SLOT;
        #pragma unroll
        for (int s = 0; s < 4; s++) {
            FragA af[2];
            FragBc bf[4];
            #pragma unroll
            for (int ii = 0; ii < 2; ii++)
                wmma::load_matrix_sync(af[ii], &As[(mw + ii * 16) * LDH + s * 16], LDH);
            #pragma unroll
            for (int j = 0; j < 4; j++)
                wmma::load_matrix_sync(bf[j], &Bs[(nw + j * 16) * LDH + s * 16], LDH);
            #pragma unroll
            for (int ii = 0; ii < 2; ii++)
                #pragma unroll
                for (int j = 0; j < 4; j++)
                    wmma::mma_sync(acc[ii][j], af[ii], bf[j], acc[ii][j]);
        }
        sCur = (sCur == 2) ? 0 : sCur + 1;
    }
    __syncthreads();
    const float* bp = fc1b + e * DFF;
    float* stage = reinterpret_cast<float*>(dynsm) + wid * 320;
    const int er = lane >> 1, ec0 = (lane & 1) * 8;
    #pragma unroll
    for (int i = 0; i < 2; i++) {
        #pragma unroll
        for (int j = 0; j < 4; j++) {
            wmma::store_matrix_sync(stage, acc[i][j], 20, wmma::mem_row_major);
            __syncwarp();
            int m = m0 + mw + i * 16 + er;
            if (m < cnt) {
                int n = n0 + nw + j * 16 + ec0;
                float vals[8];
                #pragma unroll
                for (int q = 0; q < 8; q++) {
                    float h = stage[er * 20 + ec0 + q] + bp[n + q];
                    vals[q] = h * h / (1.f + __expf(-h));   // h * silu(h)
                }
                __half2* op = reinterpret_cast<__half2*>(&g_act[((long long)e * NN + m) * DFF + n]);
                op[0] = __floats2half2_rn(vals[0], vals[1]);
                op[1] = __floats2half2_rn(vals[2], vals[3]);
                op[2] = __floats2half2_rn(vals[4], vals[5]);
                op[3] = __floats2half2_rn(vals[6], vals[7]);
            }
            __syncwarp();
        }
    }
}

// ========== gathered expert FC2 + weighted scatter-add, fp16 wmma, 3-stage ==========
__global__ __launch_bounds__(256) void k_fc2(const __half* __restrict__ fc2w,
                                             const float* __restrict__ fc2b,
                                             float* __restrict__ out) {
    extern __shared__ __half dynsm[];
    int e = blockIdx.z;
    int cnt = g_cursor[e];
    int m0 = blockIdx.x * 128;
    if (m0 >= cnt) return;
    int n0 = blockIdx.y * 128;
    const __half* Aa = g_act + (long long)e * NN * DFF;
    const __half* Bw = fc2w + (long long)e * Cc * DFF;
    const int tid = threadIdx.x, wid = tid >> 5, lane = tid & 31;
    const int mw = (wid >> 1) * 32, nw = (wid & 1) * 64;
    FragC acc[2][4];
    #pragma unroll
    for (int i = 0; i < 2; i++)
        #pragma unroll
        for (int j = 0; j < 4; j++) wmma::fill_fragment(acc[i][j], 0.f);

    const int nIter = DFF / KT;
    #pragma unroll
    for (int p = 0; p < 2; p++) {
        int k0 = p * KT;
        __half* As = dynsm + p * SLOT;
        __half* Bs = dynsm + 3 * SLOT + p * SLOT;
        #pragma unroll
        for (int rep = 0; rep < 4; rep++) {
            int v = rep * 256 + tid, r = v >> 3, seg = v & 7;
            cp16p(&As[r * LDH + seg * 8], &Aa[(long long)(m0 + r) * DFF + k0 + seg * 8],
                  m0 + r < cnt);
            cp16(&Bs[r * LDH + seg * 8], &Bw[(long long)(n0 + r) * DFF + k0 + seg * 8]);
        }
        CPCOMMIT;
    }
    int sCur = 0;
    for (int i = 0; i < nIter; i++) {
        if (i + 1 < nIter) { CPWAIT1; } else { CPWAIT0; }
        __syncthreads();
        if (i + 2 < nIter) {
            int sPre = sCur + 2; if (sPre >= 3) sPre -= 3;
            int k0 = (i + 2) * KT;
            __half* As = dynsm + sPre * SLOT;
            __half* Bs = dynsm + 3 * SLOT + sPre * SLOT;
            #pragma unroll
            for (int rep = 0; rep < 4; rep++) {
                int v = rep * 256 + tid, r = v >> 3, seg = v & 7;
                cp16p(&As[r * LDH + seg * 8], &Aa[(long long)(m0 + r) * DFF + k0 + seg * 8],
                      m0 + r < cnt);
                cp16(&Bs[r * LDH + seg * 8], &Bw[(long long)(n0 + r) * DFF + k0 + seg * 8]);
            }
            CPCOMMIT;
        }
        __half* As = dynsm + sCur * SLOT;
        __half* Bs = dynsm + 3 * SLOT + sCur * SLOT;
        #pragma unroll
        for (int s = 0; s < 4; s++) {
            FragA af[2];
            FragBc bf[4];
            #pragma unroll
            for (int ii = 0; ii < 2; ii++)
                wmma::load_matrix_sync(af[ii], &As[(mw + ii * 16) * LDH + s * 16], LDH);
            #pragma unroll
            for (int j = 0; j < 4; j++)
                wmma::load_matrix_sync(bf[j], &Bs[(nw + j * 16) * LDH + s * 16], LDH);
            #pragma unroll
            for (int ii = 0; ii < 2; ii++)
                #pragma unroll
                for (int j = 0; j < 4; j++)
                    wmma::mma_sync(acc[ii][j], af[ii], bf[j], acc[ii][j]);
        }
        sCur = (sCur == 2) ? 0 : sCur + 1;
    }
    __syncthreads();
    const float* bp = fc2b + e * Cc;
    float* stage = reinterpret_cast<float*>(dynsm) + wid * 320;
    const int er = lane >> 1, ec0 = (lane & 1) * 8;
    #pragma unroll
    for (int i = 0; i < 2; i++) {
        #pragma unroll
        for (int j = 0; j < 4; j++) {
            wmma::store_matrix_sync(stage, acc[i][j], 20, wmma::mem_row_major);
            __syncwarp();
            int m = m0 + mw + i * 16 + er;
            if (m < cnt) {
                int tk = g_tok[e * NN + m];
                float w = g_wgt[e * NN + m] * 0.5f;   // * RATIO
                int n = n0 + nw + j * 16 + ec0;
                #pragma unroll
                for (int q = 0; q < 8; q++) {
                    atomicAdd(&out[(long long)tk * Cc + n + q],
                              (stage[er * 20 + ec0 + q] + bp[n + q]) * w);
                }
            }
            __syncwarp();
        }
    }
}

// ---------------- launch ----------------
extern "C" void kernel_launch(void* const* d_in, const int* in_sizes, int n_in,
                              void* d_out, int out_size) {
    (void)in_sizes; (void)n_in; (void)out_size;
    const float* x       = (const float*)d_in[0];
    const float* qkv_w   = (const float*)d_in[1];
    const float* qkv_b   = (const float*)d_in[2];
    const float* aware_w = (const float*)d_in[3];
    const float* aware_b = (const float*)d_in[4];
    const float* dyn     = (const float*)d_in[5];
    const float* mw      = (const float*)d_in[6];
    const float* mb      = (const float*)d_in[7];
    const float* lng     = (const float*)d_in[8];
    const float* lnb     = (const float*)d_in[9];
    const float* gw      = (const float*)d_in[10];
    const float* f1w     = (const float*)d_in[11];
    const float* f1b     = (const float*)d_in[12];
    const float* f2w     = (const float*)d_in[13];
    const float* f2b     = (const float*)d_in[14];
    float* out = (float*)d_out;

    cudaFuncSetAttribute(k_gemm_abT,     cudaFuncAttributeMaxDynamicSharedMemorySize, SMEM_ABT);
    cudaFuncSetAttribute(k_gemm_ab_silu, cudaFuncAttributeMaxDynamicSharedMemorySize, SMEM_AV);
    cudaFuncSetAttribute(k_fc1,          cudaFuncAttributeMaxDynamicSharedMemorySize, SMEM_ABT);
    cudaFuncSetAttribute(k_fc2,          cudaFuncAttributeMaxDynamicSharedMemorySize, SMEM_ABT);

    __half *catp, *qkvp, *scoresp, *attnp;
    float *yp, *scalep;
    __half *rxp, *rqwp, *rmwp, *rf1p, *rf2p;
    cudaGetSymbolAddress((void**)&catp,    g_cat);
    cudaGetSymbolAddress((void**)&qkvp,    g_qkv);
    cudaGetSymbolAddress((void**)&scoresp, g_scores);
    cudaGetSymbolAddress((void**)&attnp,   g_attn);
    cudaGetSymbolAddress((void**)&yp,      g_y);
    cudaGetSymbolAddress((void**)&scalep,  g_scale);
    cudaGetSymbolAddress((void**)&rxp,     r_x);
    cudaGetSymbolAddress((void**)&rqwp,    r_qkvw);
    cudaGetSymbolAddress((void**)&rmwp,    r_mw);
    cudaGetSymbolAddress((void**)&rf1p,    r_f1w);
    cudaGetSymbolAddress((void**)&rf2p,    r_f2w);

    // float -> half conversion of all harness-provided GEMM operands
    k_cvt<<<1024, 256>>>((const float4*)x,     (uint2*)rxp,  NN*Cc/4);
    k_cvt<<<2048, 256>>>((const float4*)qkv_w, (uint2*)rqwp, Pp*C3*Cc/4);
    k_cvt<<<1024, 256>>>((const float4*)mw,    (uint2*)rmwp, Cc*C3/4);
    k_cvt<<<2048, 256>>>((const float4*)f1w,   (uint2*)rf1p, Ee*DFF*Cc/4);
    k_cvt<<<2048, 256>>>((const float4*)f2w,   (uint2*)rf2p, Ee*Cc*DFF/4);

    for (int i = 0; i < Pp; i++) {
        const __half* xin = (i == 0) ? rxp : (catp + (i - 1) * Cc);
        int ldx = (i == 0) ? Cc : C3;

        if (i == 0) k_colmean_f<<<dim3(Cc / 256, Bb), 256>>>(x, Cc);
        else        k_colmean_h<<<dim3(Cc / 256, Bb), 256>>>(catp + (i - 1) * Cc, C3);
        k_aware<<<Bb * Hh, 256>>>(aware_w + (long long)i * Hh * Cc,
                                  aware_b + i * Hh, dyn + i);
        // qkv: (2048 x 1024) @ (3072 x 1024)^T + b -> g_qkv (half)
        k_gemm_abT<<<dim3(NN / 128, C3 / 128, 1), 256, SMEM_ABT>>>(
            xin, ldx, 0, 0,
            rqwp + (long long)i * C3 * Cc, Cc, 0, 0,
            qkv_b + (long long)i * C3,
            qkvp, C3, 0, 0,
            Cc, 1, nullptr, nullptr, 0, 0, 1);
        // scores: per (b,h): Q(1024x64) @ K^T, scaled -> g_scores (half)
        k_gemm_abT<<<dim3(Tt / 128, Tt / 128, Bb * Hh), 256, SMEM_ABT>>>(
            qkvp,       C3, (long long)Tt * C3, Dd,
            qkvp + Cc,  C3, (long long)Tt * C3, Dd,
            nullptr,
            scoresp, Tt, (long long)Hh * Tt * Tt, (long long)Tt * Tt,
            Dd, Hh, scalep, nullptr, 0, 0, 1);
        // softmax + prior recurrence (vectorized, half in/out)
        k_softmax_prior<<<Bb * Hh * Tt, 256>>>(i);
        // AV: attn(1024x1024) @ V(1024x64), silu -> g_cat[:, i*C ...] (half)
        k_gemm_ab_silu<<<dim3(Tt / 128, 1, Bb * Hh), 256, SMEM_AV>>>(
            attnp,          Tt, (long long)Hh * Tt * Tt, (long long)Tt * Tt,
            qkvp + 2 * Cc,  C3, (long long)Tt * C3, Dd,
            catp + i * Cc,  C3, (long long)Tt * C3, Dd,
            Tt, Hh);
    }

    // merger: (2048 x 3072) @ (1024 x 3072)^T + b + residual(exact x) -> g_y (float)
    k_gemm_abT<<<dim3(NN / 128, Cc / 128, 1), 256, SMEM_ABT>>>(
        catp, C3, 0, 0,
        rmwp, C3, 0, 0,
        mb,
        yp, Cc, 0, 0,
        C3, 1, nullptr, x, Cc, 0, 0);

    k_layernorm<<<NN, 256>>>(lng, lnb, out);   // g_xn half copy, d_out exact
    k_zero<<<1, 32>>>();
    k_gate<<<NN, 256>>>(gw);
    k_fc1<<<dim3(NN / 128, DFF / 128, Ee), 256, SMEM_ABT>>>(rf1p, f1b);
    k_fc2<<<dim3(NN / 128, Cc / 128, Ee), 256, SMEM_ABT>>>(rf2p, f2b, out);
}

// round 14
// speedup vs baseline: 2.4518x; 1.0843x over previous
#include <cuda_runtime.h>
#include <cuda_fp16.h>
#include <mma.h>
using namespace nvcuda;

#define Bb   2
#define Tt   1024
#define Cc   1024
#define Hh   16
#define Dd   64
#define Pp   3
#define Ee   8
#define DFF  1024
#define NN   (Bb*Tt)          // 2048 tokens
#define C3   (3*Cc)           // 3072

// ---------------- scratch (static device allocations) ----------------
__device__ __half g_qkv[NN*C3];
__device__ __half g_cat[NN*C3];
__device__ __half g_scores[Bb*Hh*Tt*Tt];
__device__ __half g_attn[Bb*Hh*Tt*Tt];
__device__ float  g_y[NN*Cc];
__device__ __half g_xn[NN*Cc];          // half copy for GEMM/gate inputs
__device__ float  g_mean[Bb*Cc];
__device__ float  g_scale[Bb*Hh];
__device__ int    g_cursor[Ee];
__device__ int    g_tok[Ee*NN];
__device__ float  g_wgt[Ee*NN];
__device__ __half g_act[Ee*NN*DFF];
// half copies of harness inputs (converted once per launch)
__device__ __half r_x[NN*Cc];
__device__ __half r_qkvw[Pp*C3*Cc];
__device__ __half r_mw[Cc*C3];
__device__ __half r_f1w[Ee*DFF*Cc];
__device__ __half r_f2w[Ee*Cc*DFF];

typedef wmma::fragment<wmma::matrix_a, 16, 16, 16, __half, wmma::row_major> FragA;
typedef wmma::fragment<wmma::matrix_b, 16, 16, 16, __half, wmma::col_major> FragBc;
typedef wmma::fragment<wmma::matrix_b, 16, 16, 16, __half, wmma::row_major> FragBr;
typedef wmma::fragment<wmma::accumulator, 16, 16, 16, float> FragC;

// ---------------- cp.async helpers ----------------
__device__ __forceinline__ void cp16(void* dst, const void* src) {
    unsigned ds = (unsigned)__cvta_generic_to_shared(dst);
    asm volatile("cp.async.cg.shared.global [%0], [%1], 16;" :: "r"(ds), "l"(src));
}
__device__ __forceinline__ void cp16p(void* dst, const void* src, bool pred) {
    unsigned ds = (unsigned)__cvta_generic_to_shared(dst);
    int sz = pred ? 16 : 0;
    asm volatile("cp.async.cg.shared.global [%0], [%1], 16, %2;" :: "r"(ds), "l"(src), "r"(sz));
}
#define CPCOMMIT asm volatile("cp.async.commit_group;")
#define CPWAIT0  asm volatile("cp.async.wait_group 0;")
#define CPWAIT1  asm volatile("cp.async.wait_group 1;")

#define KT   64                   // k-tile depth (halves)
#define LDH  72                   // row stride in halves (64 + 8 pad)
#define SLOT (128*LDH)            // 9216 halves per tile slot
#define SMEM_ABT (6*SLOT*2)       // 110592 B: 3 A slots + 3 B slots
#define VLD  72
#define VSLOT (64*VLD)            // 4608 halves
#define SMEM_AV ((3*SLOT + 3*VSLOT)*2)   // 82944 B

// ---------------- block reductions (8 warps) ----------------
__device__ __forceinline__ float blockReduceSum(float v) {
    __shared__ float sh[8];
    int lane = threadIdx.x & 31, w = threadIdx.x >> 5;
    #pragma unroll
    for (int o = 16; o; o >>= 1) v += __shfl_xor_sync(0xffffffffu, v, o);
    if (lane == 0) sh[w] = v;
    __syncthreads();
    float r = 0.f;
    #pragma unroll
    for (int i = 0; i < 8; i++) r += sh[i];
    __syncthreads();
    return r;
}

// ---------------- fused float -> half convert (5 segments) ----------------
__global__ void k_cvt5(
    const float4* __restrict__ s0, uint2* __restrict__ d0, int n0,
    const float4* __restrict__ s1, uint2* __restrict__ d1, int n1,
    const float4* __restrict__ s2, uint2* __restrict__ d2, int n2,
    const float4* __restrict__ s3, uint2* __restrict__ d3, int n3,
    const float4* __restrict__ s4, uint2* __restrict__ d4, int n4)
{
    const float4* s; uint2* d; int n;
    switch (blockIdx.y) {
        case 0:  s = s0; d = d0; n = n0; break;
        case 1:  s = s1; d = d1; n = n1; break;
        case 2:  s = s2; d = d2; n = n2; break;
        case 3:  s = s3; d = d3; n = n3; break;
        default: s = s4; d = d4; n = n4; break;
    }
    for (int i = blockIdx.x * blockDim.x + threadIdx.x; i < n; i += gridDim.x * blockDim.x) {
        float4 t = s[i];
        __half2 h0 = __floats2half2_rn(t.x, t.y);
        __half2 h1 = __floats2half2_rn(t.z, t.w);
        uint2 o;
        o.x = *reinterpret_cast<unsigned*>(&h0);
        o.y = *reinterpret_cast<unsigned*>(&h1);
        d[i] = o;
    }
}

// ========== generic C = A @ B^T, 128x128 tiles, fp16 wmma, 3-stage cp.async ==========
__global__ __launch_bounds__(256) void k_gemm_abT(
    const __half* __restrict__ A, int lda, long long sA1, long long sA2,
    const __half* __restrict__ B, int ldb, long long sB1, long long sB2,
    const float* __restrict__ bias,
    void* __restrict__ Cv, int ldc, long long sC1, long long sC2,
    int K, int zdiv,
    const float* __restrict__ scale_z,
    const float* __restrict__ addsrc, int ldadd,
    int act, int out_half)
{
    extern __shared__ __half dynsm[];
    int z = blockIdx.z, z1 = z / zdiv, z2 = z % zdiv;
    A += z1 * sA1 + z2 * sA2;
    B += z1 * sB1 + z2 * sB2;
    const int m0 = blockIdx.x * 128, n0 = blockIdx.y * 128;
    const int tid = threadIdx.x, wid = tid >> 5, lane = tid & 31;
    const int mw = (wid >> 1) * 32, nw = (wid & 1) * 64;

    FragC acc[2][4];
    #pragma unroll
    for (int i = 0; i < 2; i++)
        #pragma unroll
        for (int j = 0; j < 4; j++) wmma::fill_fragment(acc[i][j], 0.f);

    const int nIter = K / KT;
    #pragma unroll
    for (int p = 0; p < 2; p++) {
        if (p < nIter) {
            int k0 = p * KT;
            __half* As = dynsm + p * SLOT;
            __half* Bs = dynsm + 3 * SLOT + p * SLOT;
            #pragma unroll
            for (int rep = 0; rep < 4; rep++) {
                int v = rep * 256 + tid, r = v >> 3, seg = v & 7;
                cp16(&As[r * LDH + seg * 8], &A[(long long)(m0 + r) * lda + k0 + seg * 8]);
                cp16(&Bs[r * LDH + seg * 8], &B[(long long)(n0 + r) * ldb + k0 + seg * 8]);
            }
            CPCOMMIT;
        }
    }
    int sCur = 0;
    for (int i = 0; i < nIter; i++) {
        if (i + 1 < nIter) { CPWAIT1; } else { CPWAIT0; }
        __syncthreads();
        if (i + 2 < nIter) {
            int sPre = sCur + 2; if (sPre >= 3) sPre -= 3;
            int k0 = (i + 2) * KT;
            __half* As = dynsm + sPre * SLOT;
            __half* Bs = dynsm + 3 * SLOT + sPre * SLOT;
            #pragma unroll
            for (int rep = 0; rep < 4; rep++) {
                int v = rep * 256 + tid, r = v >> 3, seg = v & 7;
                cp16(&As[r * LDH + seg * 8], &A[(long long)(m0 + r) * lda + k0 + seg * 8]);
                cp16(&Bs[r * LDH + seg * 8], &B[(long long)(n0 + r) * ldb + k0 + seg * 8]);
            }
            CPCOMMIT;
        }
        __half* As = dynsm + sCur * SLOT;
        __half* Bs = dynsm + 3 * SLOT + sCur * SLOT;
        #pragma unroll
        for (int s = 0; s < 4; s++) {
            FragA af[2];
            FragBc bf[4];
            #pragma unroll
            for (int ii = 0; ii < 2; ii++)
                wmma::load_matrix_sync(af[ii], &As[(mw + ii * 16) * LDH + s * 16], LDH);
            #pragma unroll
            for (int j = 0; j < 4; j++)
                wmma::load_matrix_sync(bf[j], &Bs[(nw + j * 16) * LDH + s * 16], LDH);
            #pragma unroll
            for (int ii = 0; ii < 2; ii++)
                #pragma unroll
                for (int j = 0; j < 4; j++)
                    wmma::mma_sync(acc[ii][j], af[ii], bf[j], acc[ii][j]);
        }
        sCur = (sCur == 2) ? 0 : sCur + 1;
    }
    __syncthreads();   // protect staging region from lagging warps
    float sc = scale_z ? scale_z[z] : 1.f;
    float* stage = reinterpret_cast<float*>(dynsm) + wid * 320;   // 16x20 fp32 per warp
    const int er = lane >> 1, ec0 = (lane & 1) * 8;
    #pragma unroll
    for (int i = 0; i < 2; i++) {
        #pragma unroll
        for (int j = 0; j < 4; j++) {
            wmma::store_matrix_sync(stage, acc[i][j], 20, wmma::mem_row_major);
            __syncwarp();
            int row = m0 + mw + i * 16 + er;
            int col = n0 + nw + j * 16 + ec0;
            float vals[8];
            #pragma unroll
            for (int q = 0; q < 8; q++) {
                float v = stage[er * 20 + ec0 + q] * sc;
                int nn = col + q;
                if (bias)   v += bias[nn];
                if (addsrc) v += addsrc[(long long)row * ldadd + nn];
                if (act)    v = v / (1.f + __expf(-v));
                vals[q] = v;
            }
            if (out_half) {
                __half2* cp = reinterpret_cast<__half2*>(
                    (__half*)Cv + z1 * sC1 + z2 * sC2 + (long long)row * ldc + col);
                cp[0] = __floats2half2_rn(vals[0], vals[1]);
                cp[1] = __floats2half2_rn(vals[2], vals[3]);
                cp[2] = __floats2half2_rn(vals[4], vals[5]);
                cp[3] = __floats2half2_rn(vals[6], vals[7]);
            } else {
                float* cf = (float*)Cv + z1 * sC1 + z2 * sC2 + (long long)row * ldc + col;
                *reinterpret_cast<float4*>(cf)     = make_float4(vals[0], vals[1], vals[2], vals[3]);
                *reinterpret_cast<float4*>(cf + 4) = make_float4(vals[4], vals[5], vals[6], vals[7]);
            }
            __syncwarp();
        }
    }
}

// ========== C = A @ B (row-major B, N=64), silu epilogue (AV), fp16 ==========
__global__ __launch_bounds__(256) void k_gemm_ab_silu(
    const __half* __restrict__ A, int lda, long long sA1, long long sA2,
    const __half* __restrict__ B, int ldb, long long sB1, long long sB2,
    __half* __restrict__ C, int ldc, long long sC1, long long sC2,
    int K, int zdiv)
{
    extern __shared__ __half dynsm[];
    int z = blockIdx.z, z1 = z / zdiv, z2 = z % zdiv;
    A += z1 * sA1 + z2 * sA2;
    B += z1 * sB1 + z2 * sB2;
    C += z1 * sC1 + z2 * sC2;
    const int m0 = blockIdx.x * 128;
    const int tid = threadIdx.x, wid = tid >> 5, lane = tid & 31;
    const int mw = (wid >> 1) * 32, nw = (wid & 1) * 32;
    __half* Vbase = dynsm + 3 * SLOT;

    FragC acc[2][2];
    #pragma unroll
    for (int i = 0; i < 2; i++)
        #pragma unroll
        for (int j = 0; j < 2; j++) wmma::fill_fragment(acc[i][j], 0.f);

    const int nIter = K / KT;
    #pragma unroll
    for (int p = 0; p < 2; p++) {
        if (p < nIter) {
            int k0 = p * KT;
            __half* As = dynsm + p * SLOT;
            __half* Vs = Vbase + p * VSLOT;
            #pragma unroll
            for (int rep = 0; rep < 4; rep++) {
                int v = rep * 256 + tid, r = v >> 3, seg = v & 7;
                cp16(&As[r * LDH + seg * 8], &A[(long long)(m0 + r) * lda + k0 + seg * 8]);
            }
            #pragma unroll
            for (int rep = 0; rep < 2; rep++) {
                int v = rep * 256 + tid, vr = v >> 3, vseg = v & 7;
                cp16(&Vs[vr * VLD + vseg * 8], &B[(long long)(k0 + vr) * ldb + vseg * 8]);
            }
            CPCOMMIT;
        }
    }
    int sCur = 0;
    for (int i = 0; i < nIter; i++) {
        if (i + 1 < nIter) { CPWAIT1; } else { CPWAIT0; }
        __syncthreads();
        if (i + 2 < nIter) {
            int sPre = sCur + 2; if (sPre >= 3) sPre -= 3;
            int k0 = (i + 2) * KT;
            __half* As = dynsm + sPre * SLOT;
            __half* Vs = Vbase + sPre * VSLOT;
            #pragma unroll
            for (int rep = 0; rep < 4; rep++) {
                int v = rep * 256 + tid, r = v >> 3, seg = v & 7;
                cp16(&As[r * LDH + seg * 8], &A[(long long)(m0 + r) * lda + k0 + seg * 8]);
            }
            #pragma unroll
            for (int rep = 0; rep < 2; rep++) {
                int v = rep * 256 + tid, vr = v >> 3, vseg = v & 7;
                cp16(&Vs[vr * VLD + vseg * 8], &B[(long long)(k0 + vr) * ldb + vseg * 8]);
            }
            CPCOMMIT;
        }
        __half* As = dynsm + sCur * SLOT;
        __half* Vs = Vbase + sCur * VSLOT;
        #pragma unroll
        for (int s = 0; s < 4; s++) {
            FragA af[2];
            FragBr bf[2];
            #pragma unroll
            for (int ii = 0; ii < 2; ii++)
                wmma::load_matrix_sync(af[ii], &As[(mw + ii * 16) * LDH + s * 16], LDH);
            #pragma unroll
            for (int j = 0; j < 2; j++)
                wmma::load_matrix_sync(bf[j], &Vs[(s * 16) * VLD + nw + j * 16], VLD);
            #pragma unroll
            for (int ii = 0; ii < 2; ii++)
                #pragma unroll
                for (int j = 0; j < 2; j++)
                    wmma::mma_sync(acc[ii][j], af[ii], bf[j], acc[ii][j]);
        }
        sCur = (sCur == 2) ? 0 : sCur + 1;
    }
    __syncthreads();
    float* stage = reinterpret_cast<float*>(dynsm) + wid * 320;
    const int er = lane >> 1, ec0 = (lane & 1) * 8;
    #pragma unroll
    for (int i = 0; i < 2; i++) {
        #pragma unroll
        for (int j = 0; j < 2; j++) {
            wmma::store_matrix_sync(stage, acc[i][j], 20, wmma::mem_row_major);
            __syncwarp();
            int row = m0 + mw + i * 16 + er;
            int col = nw + j * 16 + ec0;
            float vals[8];
            #pragma unroll
            for (int q = 0; q < 8; q++) {
                float v = stage[er * 20 + ec0 + q];
                vals[q] = v / (1.f + __expf(-v));
            }
            __half2* cp = reinterpret_cast<__half2*>(&C[(long long)row * ldc + col]);
            cp[0] = __floats2half2_rn(vals[0], vals[1]);
            cp[1] = __floats2half2_rn(vals[2], vals[3]);
            cp[2] = __floats2half2_rn(vals[4], vals[5]);
            cp[3] = __floats2half2_rn(vals[6], vals[7]);
            __syncwarp();
        }
    }
}

// ---------------- small kernels ----------------
__global__ void k_colmean_f(const float* __restrict__ x, int lda) {
    int b = blockIdx.y;
    int c = blockIdx.x * 256 + threadIdx.x;
    const float* p = x + (long long)b * Tt * lda + c;
    float s = 0.f;
    for (int t = 0; t < Tt; t++) s += p[(long long)t * lda];
    g_mean[b * Cc + c] = s * (1.f / Tt);
}
__global__ void k_colmean_h(const __half* __restrict__ x, int lda) {
    int b = blockIdx.y;
    int c = blockIdx.x * 256 + threadIdx.x;
    const __half* p = x + (long long)b * Tt * lda + c;
    float s = 0.f;
    for (int t = 0; t < Tt; t++) s += __half2float(p[(long long)t * lda]);
    g_mean[b * Cc + c] = s * (1.f / Tt);
}

__global__ void k_aware(const float* __restrict__ aw, const float* __restrict__ ab,
                        const float* __restrict__ ds) {
    int b = blockIdx.x >> 4, h = blockIdx.x & 15;
    const float* m = g_mean + b * Cc;
    const float* w = aw + h * Cc;
    float s = 0.f;
    for (int c = threadIdx.x; c < Cc; c += 256) s += m[c] * w[c];
    s = blockReduceSum(s);
    if (threadIdx.x == 0) g_scale[b * Hh + h] = ds[0] * (s + ab[h]);
}

// warp-per-row softmax + prior: 8 warps/block, each warp owns one 1024-row.
// lane holds 32 halves via 4x uint4; reductions are pure shfl (no barriers).
__global__ void k_softmax_prior(int phase) {
    long long row = blockIdx.x * 8LL + (threadIdx.x >> 5);
    int lane = threadIdx.x & 31;
    const uint4* s = reinterpret_cast<const uint4*>(g_scores) + row * 128;
    uint4* a = reinterpret_cast<uint4*>(g_attn) + row * 128;
    float v[32];
    #pragma unroll
    for (int k = 0; k < 4; k++) {
        uint4 t = s[lane + 32 * k];
        const __half2* hp = reinterpret_cast<const __half2*>(&t);
        #pragma unroll
        for (int j = 0; j < 4; j++) {
            float2 f = __half22float2(hp[j]);
            v[k * 8 + j * 2]     = f.x;
            v[k * 8 + j * 2 + 1] = f.y;
        }
    }
    float mx = v[0];
    #pragma unroll
    for (int i = 1; i < 32; i++) mx = fmaxf(mx, v[i]);
    #pragma unroll
    for (int o = 16; o; o >>= 1) mx = fmaxf(mx, __shfl_xor_sync(0xffffffffu, mx, o));
    float sum = 0.f;
    #pragma unroll
    for (int i = 0; i < 32; i++) { v[i] = __expf(v[i] - mx); sum += v[i]; }
    #pragma unroll
    for (int o = 16; o; o >>= 1) sum += __shfl_xor_sync(0xffffffffu, sum, o);
    float inv = 1.f / sum;
    #pragma unroll
    for (int i = 0; i < 32; i++) v[i] *= inv;
    if (phase) {
        #pragma unroll
        for (int k = 0; k < 4; k++) {
            uint4 t = a[lane + 32 * k];
            const __half2* hp = reinterpret_cast<const __half2*>(&t);
            #pragma unroll
            for (int j = 0; j < 4; j++) {
                float2 f = __half22float2(hp[j]);
                v[k * 8 + j * 2]     += 0.3f * f.x;
                v[k * 8 + j * 2 + 1] += 0.3f * f.y;
            }
        }
    }
    #pragma unroll
    for (int k = 0; k < 4; k++) {
        uint4 t;
        __half2* hp = reinterpret_cast<__half2*>(&t);
        #pragma unroll
        for (int j = 0; j < 4; j++)
            hp[j] = __floats2half2_rn(v[k * 8 + j * 2], v[k * 8 + j * 2 + 1]);
        a[lane + 32 * k] = t;
    }
}

__global__ void k_layernorm(const float* __restrict__ gam, const float* __restrict__ bet,
                            float* __restrict__ out) {
    int row = blockIdx.x;
    const float* y = g_y + (long long)row * Cc;
    float s = 0.f, q = 0.f;
    for (int c = threadIdx.x; c < Cc; c += 256) { float v = y[c]; s += v; q += v * v; }
    s = blockReduceSum(s);
    q = blockReduceSum(q);
    float mu = s * (1.f / Cc);
    float var = q * (1.f / Cc) - mu * mu;
    float inv = rsqrtf(var + 1e-5f);
    for (int c = threadIdx.x; c < Cc; c += 256) {
        float xn = (y[c] - mu) * inv * gam[c] + bet[c];
        g_xn[(long long)row * Cc + c] = __float2half_rn(xn);   // half copy for GEMM input
        out[(long long)row * Cc + c] = xn;                     // exact output
    }
}

__global__ void k_zero() { if (threadIdx.x < Ee) g_cursor[threadIdx.x] = 0; }

__global__ void k_gate(const float* __restrict__ gw) {
    int n = blockIdx.x;
    int wid = threadIdx.x >> 5, lane = threadIdx.x & 31;
    __shared__ float lg[Ee];
    const __half* t = g_xn + (long long)n * Cc;
    const float* w = gw + wid * Cc;
    float s = 0.f;
    for (int c = lane; c < Cc; c += 32) s += __half2float(t[c]) * w[c];
    #pragma unroll
    for (int o = 16; o; o >>= 1) s += __shfl_xor_sync(0xffffffffu, s, o);
    if (lane == 0) lg[wid] = s;
    __syncthreads();
    if (threadIdx.x == 0) {
        float mx = lg[0];
        #pragma unroll
        for (int e = 1; e < Ee; e++) mx = fmaxf(mx, lg[e]);
        float p[Ee];
        #pragma unroll
        for (int e = 0; e < Ee; e++) p[e] = __expf(lg[e] - mx);
        int i1 = 0;
        #pragma unroll
        for (int e = 1; e < Ee; e++) if (p[e] > p[i1]) i1 = e;
        int i2 = (i1 == 0) ? 1 : 0;
        #pragma unroll
        for (int e = 0; e < Ee; e++) if (e != i1 && p[e] > p[i2]) i2 = e;
        float tot = p[i1] + p[i2];
        float w1 = p[i1] / tot, w2 = p[i2] / tot;
        int p1 = atomicAdd(&g_cursor[i1], 1);
        g_tok[i1 * NN + p1] = n; g_wgt[i1 * NN + p1] = w1;
        int p2 = atomicAdd(&g_cursor[i2], 1);
        g_tok[i2 * NN + p2] = n; g_wgt[i2 * NN + p2] = w2;
    }
}

// ========== gathered expert FC1, fp16 wmma, 3-stage, a = h^2*sigmoid(h) ==========
__global__ __launch_bounds__(256) void k_fc1(const __half* __restrict__ fc1w,
                                             const float* __restrict__ fc1b) {
    extern __shared__ __half dynsm[];
    int e = blockIdx.z;
    int cnt = g_cursor[e];
    int m0 = blockIdx.x * 128;
    if (m0 >= cnt) return;
    int n0 = blockIdx.y * 128;
    const __half* Bw = fc1w + (long long)e * DFF * Cc;
    __shared__ int toks[128];
    const int tid = threadIdx.x, wid = tid >> 5, lane = tid & 31;
    const int mw = (wid >> 1) * 32, nw = (wid & 1) * 64;
    if (tid < 128) {
        int m = m0 + tid;
        toks[tid] = (m < cnt) ? g_tok[e * NN + m] : -1;
    }
    __syncthreads();
    FragC acc[2][4];
    #pragma unroll
    for (int i = 0; i < 2; i++)
        #pragma unroll
        for (int j = 0; j < 4; j++) wmma::fill_fragment(acc[i][j], 0.f);

    const int nIter = Cc / KT;
    #pragma unroll
    for (int p = 0; p < 2; p++) {
        int k0 = p * KT;
        __half* As = dynsm + p * SLOT;
        __half* Bs = dynsm + 3 * SLOT + p * SLOT;
        #pragma unroll
        for (int rep = 0; rep < 4; rep++) {
            int v = rep * 256 + tid, r = v >> 3, seg = v & 7;
            int tk = toks[r];
            cp16p(&As[r * LDH + seg * 8],
                  &g_xn[(long long)(tk < 0 ? 0 : tk) * Cc + k0 + seg * 8], tk >= 0);
            cp16(&Bs[r * LDH + seg * 8], &Bw[(long long)(n0 + r) * Cc + k0 + seg * 8]);
        }
        CPCOMMIT;
    }
    int sCur = 0;
    for (int i = 0; i < nIter; i++) {
        if (i + 1 < nIter) { CPWAIT1; } else { CPWAIT0; }
        __syncthreads();
        if (i + 2 < nIter) {
            int sPre = sCur + 2; if (sPre >= 3) sPre -= 3;
            int k0 = (i + 2) * KT;
            __half* As = dynsm + sPre * SLOT;
            __half* Bs = dynsm + 3 * SLOT + sPre * SLOT;
            #pragma unroll
            for (int rep = 0; rep < 4; rep++) {
                int v = rep * 256 + tid, r = v >> 3, seg = v & 7;
                int tk = toks[r];
                cp16p(&As[r * LDH + seg * 8],
                      &g_xn[(long long)(tk < 0 ? 0 : tk) * Cc + k0 + seg * 8], tk >= 0);
                cp16(&Bs[r * LDH + seg * 8], &Bw[(long long)(n0 + r) * Cc + k0 + seg * 8]);
            }
            CPCOMMIT;
        }
        __half* As = dynsm + sCur * SLOT;
        __half* Bs = dynsm + 3 * SLOT + sCur * SLOT;
        #pragma unroll
        for (int s = 0; s < 4; s++) {
            FragA af[2];
            FragBc bf[4];
            #pragma unroll
            for (int ii = 0; ii < 2; ii++)
                wmma::load_matrix_sync(af[ii], &As[(mw + ii * 16) * LDH + s * 16], LDH);
            #pragma unroll
            for (int j = 0; j < 4; j++)
                wmma::load_matrix_sync(bf[j], &Bs[(nw + j * 16) * LDH + s * 16], LDH);
            #pragma unroll
            for (int ii = 0; ii < 2; ii++)
                #pragma unroll
                for (int j = 0; j < 4; j++)
                    wmma::mma_sync(acc[ii][j], af[ii], bf[j], acc[ii][j]);
        }
        sCur = (sCur == 2) ? 0 : sCur + 1;
    }
    __syncthreads();
    const float* bp = fc1b + e * DFF;
    float* stage = reinterpret_cast<float*>(dynsm) + wid * 320;
    const int er = lane >> 1, ec0 = (lane & 1) * 8;
    #pragma unroll
    for (int i = 0; i < 2; i++) {
        #pragma unroll
        for (int j = 0; j < 4; j++) {
            wmma::store_matrix_sync(stage, acc[i][j], 20, wmma::mem_row_major);
            __syncwarp();
            int m = m0 + mw + i * 16 + er;
            if (m < cnt) {
                int n = n0 + nw + j * 16 + ec0;
                float vals[8];
                #pragma unroll
                for (int q = 0; q < 8; q++) {
                    float h = stage[er * 20 + ec0 + q] + bp[n + q];
                    vals[q] = h * h / (1.f + __expf(-h));   // h * silu(h)
                }
                __half2* op = reinterpret_cast<__half2*>(&g_act[((long long)e * NN + m) * DFF + n]);
                op[0] = __floats2half2_rn(vals[0], vals[1]);
                op[1] = __floats2half2_rn(vals[2], vals[3]);
                op[2] = __floats2half2_rn(vals[4], vals[5]);
                op[3] = __floats2half2_rn(vals[6], vals[7]);
            }
            __syncwarp();
        }
    }
}

// ========== gathered expert FC2 + weighted scatter-add, fp16 wmma, 3-stage ==========
__global__ __launch_bounds__(256) void k_fc2(const __half* __restrict__ fc2w,
                                             const float* __restrict__ fc2b,
                                             float* __restrict__ out) {
    extern __shared__ __half dynsm[];
    int e = blockIdx.z;
    int cnt = g_cursor[e];
    int m0 = blockIdx.x * 128;
    if (m0 >= cnt) return;
    int n0 = blockIdx.y * 128;
    const __half* Aa = g_act + (long long)e * NN * DFF;
    const __half* Bw = fc2w + (long long)e * Cc * DFF;
    const int tid = threadIdx.x, wid = tid >> 5, lane = tid & 31;
    const int mw = (wid >> 1) * 32, nw = (wid & 1) * 64;
    FragC acc[2][4];
    #pragma unroll
    for (int i = 0; i < 2; i++)
        #pragma unroll
        for (int j = 0; j < 4; j++) wmma::fill_fragment(acc[i][j], 0.f);

    const int nIter = DFF / KT;
    #pragma unroll
    for (int p = 0; p < 2; p++) {
        int k0 = p * KT;
        __half* As = dynsm + p * SLOT;
        __half* Bs = dynsm + 3 * SLOT + p * SLOT;
        #pragma unroll
        for (int rep = 0; rep < 4; rep++) {
            int v = rep * 256 + tid, r = v >> 3, seg = v & 7;
            cp16p(&As[r * LDH + seg * 8], &Aa[(long long)(m0 + r) * DFF + k0 + seg * 8],
                  m0 + r < cnt);
            cp16(&Bs[r * LDH + seg * 8], &Bw[(long long)(n0 + r) * DFF + k0 + seg * 8]);
        }
        CPCOMMIT;
    }
    int sCur = 0;
    for (int i = 0; i < nIter; i++) {
        if (i + 1 < nIter) { CPWAIT1; } else { CPWAIT0; }
        __syncthreads();
        if (i + 2 < nIter) {
            int sPre = sCur + 2; if (sPre >= 3) sPre -= 3;
            int k0 = (i + 2) * KT;
            __half* As = dynsm + sPre * SLOT;
            __half* Bs = dynsm + 3 * SLOT + sPre * SLOT;
            #pragma unroll
            for (int rep = 0; rep < 4; rep++) {
                int v = rep * 256 + tid, r = v >> 3, seg = v & 7;
                cp16p(&As[r * LDH + seg * 8], &Aa[(long long)(m0 + r) * DFF + k0 + seg * 8],
                      m0 + r < cnt);
                cp16(&Bs[r * LDH + seg * 8], &Bw[(long long)(n0 + r) * DFF + k0 + seg * 8]);
            }
            CPCOMMIT;
        }
        __half* As = dynsm + sCur * SLOT;
        __half* Bs = dynsm + 3 * SLOT + sCur * SLOT;
        #pragma unroll
        for (int s = 0; s < 4; s++) {
            FragA af[2];
            FragBc bf[4];
            #pragma unroll
            for (int ii = 0; ii < 2; ii++)
                wmma::load_matrix_sync(af[ii], &As[(mw + ii * 16) * LDH + s * 16], LDH);
            #pragma unroll
            for (int j = 0; j < 4; j++)
                wmma::load_matrix_sync(bf[j], &Bs[(nw + j * 16) * LDH + s * 16], LDH);
            #pragma unroll
            for (int ii = 0; ii < 2; ii++)
                #pragma unroll
                for (int j = 0; j < 4; j++)
                    wmma::mma_sync(acc[ii][j], af[ii], bf[j], acc[ii][j]);
        }
        sCur = (sCur == 2) ? 0 : sCur + 1;
    }
    __syncthreads();
    const float* bp = fc2b + e * Cc;
    float* stage = reinterpret_cast<float*>(dynsm) + wid * 320;
    const int er = lane >> 1, ec0 = (lane & 1) * 8;
    #pragma unroll
    for (int i = 0; i < 2; i++) {
        #pragma unroll
        for (int j = 0; j < 4; j++) {
            wmma::store_matrix_sync(stage, acc[i][j], 20, wmma::mem_row_major);
            __syncwarp();
            int m = m0 + mw + i * 16 + er;
            if (m < cnt) {
                int tk = g_tok[e * NN + m];
                float w = g_wgt[e * NN + m] * 0.5f;   // * RATIO
                int n = n0 + nw + j * 16 + ec0;
                #pragma unroll
                for (int q = 0; q < 8; q++) {
                    atomicAdd(&out[(long long)tk * Cc + n + q],
                              (stage[er * 20 + ec0 + q] + bp[n + q]) * w);
                }
            }
            __syncwarp();
        }
    }
}

// ---------------- launch ----------------
extern "C" void kernel_launch(void* const* d_in, const int* in_sizes, int n_in,
                              void* d_out, int out_size) {
    (void)in_sizes; (void)n_in; (void)out_size;
    const float* x       = (const float*)d_in[0];
    const float* qkv_w   = (const float*)d_in[1];
    const float* qkv_b   = (const float*)d_in[2];
    const float* aware_w = (const float*)d_in[3];
    const float* aware_b = (const float*)d_in[4];
    const float* dyn     = (const float*)d_in[5];
    const float* mw      = (const float*)d_in[6];
    const float* mb      = (const float*)d_in[7];
    const float* lng     = (const float*)d_in[8];
    const float* lnb     = (const float*)d_in[9];
    const float* gw      = (const float*)d_in[10];
    const float* f1w     = (const float*)d_in[11];
    const float* f1b     = (const float*)d_in[12];
    const float* f2w     = (const float*)d_in[13];
    const float* f2b     = (const float*)d_in[14];
    float* out = (float*)d_out;

    cudaFuncSetAttribute(k_gemm_abT,     cudaFuncAttributeMaxDynamicSharedMemorySize, SMEM_ABT);
    cudaFuncSetAttribute(k_gemm_ab_silu, cudaFuncAttributeMaxDynamicSharedMemorySize, SMEM_AV);
    cudaFuncSetAttribute(k_fc1,          cudaFuncAttributeMaxDynamicSharedMemorySize, SMEM_ABT);
    cudaFuncSetAttribute(k_fc2,          cudaFuncAttributeMaxDynamicSharedMemorySize, SMEM_ABT);

    __half *catp, *qkvp, *scoresp, *attnp;
    float *yp, *scalep;
    __half *rxp, *rqwp, *rmwp, *rf1p, *rf2p;
    cudaGetSymbolAddress((void**)&catp,    g_cat);
    cudaGetSymbolAddress((void**)&qkvp,    g_qkv);
    cudaGetSymbolAddress((void**)&scoresp, g_scores);
    cudaGetSymbolAddress((void**)&attnp,   g_attn);
    cudaGetSymbolAddress((void**)&yp,      g_y);
    cudaGetSymbolAddress((void**)&scalep,  g_scale);
    cudaGetSymbolAddress((void**)&rxp,     r_x);
    cudaGetSymbolAddress((void**)&rqwp,    r_qkvw);
    cudaGetSymbolAddress((void**)&rmwp,    r_mw);
    cudaGetSymbolAddress((void**)&rf1p,    r_f1w);
    cudaGetSymbolAddress((void**)&rf2p,    r_f2w);

    // fused float -> half conversion of all harness-provided GEMM operands
    k_cvt5<<<dim3(1024, 5), 256>>>(
        (const float4*)x,     (uint2*)rxp,  NN*Cc/4,
        (const float4*)qkv_w, (uint2*)rqwp, Pp*C3*Cc/4,
        (const float4*)mw,    (uint2*)rmwp, Cc*C3/4,
        (const float4*)f1w,   (uint2*)rf1p, Ee*DFF*Cc/4,
        (const float4*)f2w,   (uint2*)rf2p, Ee*Cc*DFF/4);

    for (int i = 0; i < Pp; i++) {
        const __half* xin = (i == 0) ? rxp : (catp + (i - 1) * Cc);
        int ldx = (i == 0) ? Cc : C3;

        if (i == 0) k_colmean_f<<<dim3(Cc / 256, Bb), 256>>>(x, Cc);
        else        k_colmean_h<<<dim3(Cc / 256, Bb), 256>>>(catp + (i - 1) * Cc, C3);
        k_aware<<<Bb * Hh, 256>>>(aware_w + (long long)i * Hh * Cc,
                                  aware_b + i * Hh, dyn + i);
        // qkv: (2048 x 1024) @ (3072 x 1024)^T + b -> g_qkv (half)
        k_gemm_abT<<<dim3(NN / 128, C3 / 128, 1), 256, SMEM_ABT>>>(
            xin, ldx, 0, 0,
            rqwp + (long long)i * C3 * Cc, Cc, 0, 0,
            qkv_b + (long long)i * C3,
            qkvp, C3, 0, 0,
            Cc, 1, nullptr, nullptr, 0, 0, 1);
        // scores: per (b,h): Q(1024x64) @ K^T, scaled -> g_scores (half)
        k_gemm_abT<<<dim3(Tt / 128, Tt / 128, Bb * Hh), 256, SMEM_ABT>>>(
            qkvp,       C3, (long long)Tt * C3, Dd,
            qkvp + Cc,  C3, (long long)Tt * C3, Dd,
            nullptr,
            scoresp, Tt, (long long)Hh * Tt * Tt, (long long)Tt * Tt,
            Dd, Hh, scalep, nullptr, 0, 0, 1);
        // softmax + prior recurrence (warp-per-row, half in/out)
        k_softmax_prior<<<Bb * Hh * Tt / 8, 256>>>(i);
        // AV: attn(1024x1024) @ V(1024x64), silu -> g_cat[:, i*C ...] (half)
        k_gemm_ab_silu<<<dim3(Tt / 128, 1, Bb * Hh), 256, SMEM_AV>>>(
            attnp,          Tt, (long long)Hh * Tt * Tt, (long long)Tt * Tt,
            qkvp + 2 * Cc,  C3, (long long)Tt * C3, Dd,
            catp + i * Cc,  C3, (long long)Tt * C3, Dd,
            Tt, Hh);
    }

    // merger: (2048 x 3072) @ (1024 x 3072)^T + b + residual(exact x) -> g_y (float)
    k_gemm_abT<<<dim3(NN / 128, Cc / 128, 1), 256, SMEM_ABT>>>(
        catp, C3, 0, 0,
        rmwp, C3, 0, 0,
        mb,
        yp, Cc, 0, 0,
        C3, 1, nullptr, x, Cc, 0, 0);

    k_layernorm<<<NN, 256>>>(lng, lnb, out);   // g_xn half copy, d_out exact
    k_zero<<<1, 32>>>();
    k_gate<<<NN, 256>>>(gw);
    k_fc1<<<dim3(NN / 128, DFF / 128, Ee), 256, SMEM_ABT>>>(rf1p, f1b);
    k_fc2<<<dim3(NN / 128, Cc / 128, Ee), 256, SMEM_ABT>>>(rf2p, f2b, out);
}